// round 1
// baseline (speedup 1.0000x reference)
#include <cuda_runtime.h>
#include <cstdint>

#define B_  16
#define L_  1024
#define F_  512
#define H_  8
#define D_  64
#define U_  35
#define BH_ (B_*H_)     // 128
#define ML_ (B_*L_)     // 16384

#define INF_F __int_as_float(0x7f800000)

// -------- device scratch (no allocations allowed) --------
__device__ float g_q[(size_t)BH_*L_*D_];     // (B,H,L,D)
__device__ float g_k[(size_t)BH_*L_*D_];
__device__ float g_v[(size_t)BH_*L_*D_];
__device__ float g_M[(size_t)BH_*L_];
__device__ int   g_idx[BH_*U_];
__device__ float g_x2[(size_t)ML_*F_];       // context in (B,L,F) layout
__device__ float g_sc[(size_t)BH_*U_*L_];    // sparse scores / probs

// ============================================================
// GEMM: C[M,N] = X[M,K] @ W[N,K]^T + bias ; M=16384, N=K=512
// ATTN=1: write out[((b*H+h)*L+l)*D+d], else row-major [m*F+n]
// ============================================================
template<int ATTN>
__global__ __launch_bounds__(256)
void gemm_kernel(const float* __restrict__ X,
                 const float* __restrict__ W,
                 const float* __restrict__ bias,
                 float* __restrict__ out)
{
    __shared__ float As[32][68];
    __shared__ float Ws[32][68];
    const int tid = threadIdx.x;
    const int tx = tid & 15, ty = tid >> 4;
    const int m0 = blockIdx.y * 64;
    const int n0 = blockIdx.x * 64;
    const int lr = tid >> 3;           // 0..31
    const int lc = (tid & 7) << 2;     // 0,4,...,28

    float acc[4][4] = {};

    for (int kt = 0; kt < F_; kt += 32) {
#pragma unroll
        for (int r = 0; r < 2; r++) {
            int row = lr + r*32;
            float4 a = *(const float4*)(X + (size_t)(m0 + row)*F_ + kt + lc);
            As[lc+0][row] = a.x; As[lc+1][row] = a.y;
            As[lc+2][row] = a.z; As[lc+3][row] = a.w;
            float4 w = *(const float4*)(W + (size_t)(n0 + row)*F_ + kt + lc);
            Ws[lc+0][row] = w.x; Ws[lc+1][row] = w.y;
            Ws[lc+2][row] = w.z; Ws[lc+3][row] = w.w;
        }
        __syncthreads();
#pragma unroll
        for (int kk = 0; kk < 32; kk++) {
            float4 a4 = *(const float4*)&As[kk][ty << 2];
            float4 b4 = *(const float4*)&Ws[kk][tx << 2];
            float av[4] = {a4.x, a4.y, a4.z, a4.w};
            float bv[4] = {b4.x, b4.y, b4.z, b4.w};
#pragma unroll
            for (int i = 0; i < 4; i++)
#pragma unroll
                for (int j = 0; j < 4; j++)
                    acc[i][j] += av[i] * bv[j];
        }
        __syncthreads();
    }

    const int n = n0 + (tx << 2);
    float4 bb = *(const float4*)(bias + n);
#pragma unroll
    for (int i = 0; i < 4; i++) {
        int m = m0 + (ty << 2) + i;
        float4 r;
        r.x = acc[i][0] + bb.x;
        r.y = acc[i][1] + bb.y;
        r.z = acc[i][2] + bb.z;
        r.w = acc[i][3] + bb.w;
        if (ATTN) {
            int b = m >> 10, l = m & (L_ - 1);
            int h = n >> 6,  d = n & (D_ - 1);
            *(float4*)(out + ((size_t)(b*H_ + h)*L_ + l)*D_ + d) = r;
        } else {
            *(float4*)(out + (size_t)m*F_ + n) = r;
        }
    }
}

// ============================================================
// M[b,h,q] = max_k(q.k) - mean_k(q.k) ; fused QK + row reduce
// grid: (L/64, BH), block 256
// ============================================================
__global__ __launch_bounds__(256)
void qk_m_kernel()
{
    __shared__ float Qs[64][68];   // [d][q]
    __shared__ float Ks[64][68];   // [d][k]
    const int tid = threadIdx.x;
    const int tx = tid & 15, ty = tid >> 4;
    const int bh = blockIdx.y;
    const int q0 = blockIdx.x * 64;
    const float* qp = g_q + (size_t)bh*L_*D_;
    const float* kp = g_k + (size_t)bh*L_*D_;

#pragma unroll
    for (int i = 0; i < 4; i++) {
        int idx = tid + i*256;        // 0..1023
        int row = idx >> 4;           // 0..63
        int d4  = (idx & 15) << 2;
        float4 v = *(const float4*)(qp + (size_t)(q0 + row)*D_ + d4);
        Qs[d4+0][row] = v.x; Qs[d4+1][row] = v.y;
        Qs[d4+2][row] = v.z; Qs[d4+3][row] = v.w;
    }

    float rmax[4] = {-INF_F, -INF_F, -INF_F, -INF_F};
    float rsum[4] = {0.f, 0.f, 0.f, 0.f};

    for (int ktile = 0; ktile < L_; ktile += 64) {
        __syncthreads();
#pragma unroll
        for (int i = 0; i < 4; i++) {
            int idx = tid + i*256;
            int row = idx >> 4;
            int d4  = (idx & 15) << 2;
            float4 v = *(const float4*)(kp + (size_t)(ktile + row)*D_ + d4);
            Ks[d4+0][row] = v.x; Ks[d4+1][row] = v.y;
            Ks[d4+2][row] = v.z; Ks[d4+3][row] = v.w;
        }
        __syncthreads();

        float acc[4][4] = {};
#pragma unroll
        for (int d = 0; d < 64; d++) {
            float4 a4 = *(const float4*)&Qs[d][ty << 2];
            float4 b4 = *(const float4*)&Ks[d][tx << 2];
            float av[4] = {a4.x, a4.y, a4.z, a4.w};
            float bv[4] = {b4.x, b4.y, b4.z, b4.w};
#pragma unroll
            for (int i = 0; i < 4; i++)
#pragma unroll
                for (int j = 0; j < 4; j++)
                    acc[i][j] += av[i] * bv[j];
        }
#pragma unroll
        for (int i = 0; i < 4; i++) {
            float mx = fmaxf(fmaxf(acc[i][0], acc[i][1]), fmaxf(acc[i][2], acc[i][3]));
            rmax[i] = fmaxf(rmax[i], mx);
            rsum[i] += (acc[i][0] + acc[i][1]) + (acc[i][2] + acc[i][3]);
        }
    }

#pragma unroll
    for (int i = 0; i < 4; i++) {
        float m = rmax[i], s = rsum[i];
#pragma unroll
        for (int off = 8; off; off >>= 1) {
            m = fmaxf(m, __shfl_xor_sync(0xffffffffu, m, off));
            s += __shfl_xor_sync(0xffffffffu, s, off);
        }
        if (tx == 0)
            g_M[(size_t)bh*L_ + q0 + (ty << 2) + i] = m - s * (1.0f / L_);
    }
}

// ============================================================
// top-35 indices per (b,h) via iterative argmax (tie: lowest idx)
// ============================================================
__global__ __launch_bounds__(256)
void topk_kernel()
{
    __shared__ float sv[L_];
    __shared__ float rv[256];
    __shared__ int   ri[256];
    const int bh = blockIdx.x, tid = threadIdx.x;
    for (int i = tid; i < L_; i += 256) sv[i] = g_M[(size_t)bh*L_ + i];
    __syncthreads();

    for (int it = 0; it < U_; it++) {
        float bvv = -INF_F; int bii = 0;
#pragma unroll
        for (int j = 0; j < 4; j++) {
            int k = tid*4 + j;
            float v = sv[k];
            if (v > bvv) { bvv = v; bii = k; }
        }
        rv[tid] = bvv; ri[tid] = bii;
        __syncthreads();
        for (int s = 128; s; s >>= 1) {
            if (tid < s) {
                float v2 = rv[tid + s]; int i2 = ri[tid + s];
                if (v2 > rv[tid] || (v2 == rv[tid] && i2 < ri[tid])) {
                    rv[tid] = v2; ri[tid] = i2;
                }
            }
            __syncthreads();
        }
        if (tid == 0) {
            g_idx[bh*U_ + it] = ri[0];
            sv[ri[0]] = -INF_F;
        }
        __syncthreads();
    }
}

// ============================================================
// vmean broadcast: x2[b, l, h*64+d] = mean_l v[b,h,l,d]
// ============================================================
__global__ __launch_bounds__(256)
void vmean_kernel()
{
    const int bh = blockIdx.x, tid = threadIdx.x;
    const int d = tid & 63, part = tid >> 6;
    const float* vp = g_v + (size_t)bh*L_*D_;
    float acc = 0.f;
    for (int l = part*256; l < part*256 + 256; l++)
        acc += vp[(size_t)l*D_ + d];

    __shared__ float red[4][64];
    __shared__ float vm[64];
    red[part][d] = acc;
    __syncthreads();
    if (tid < 64)
        vm[tid] = (red[0][tid] + red[1][tid] + red[2][tid] + red[3][tid]) * (1.0f / L_);
    __syncthreads();

    const int b = bh >> 3, h = bh & 7;
    float* x2 = g_x2 + (size_t)b*L_*F_ + h*D_;
    for (int i = tid; i < L_*D_; i += 256) {
        int l = i >> 6, dd = i & 63;
        x2[(size_t)l*F_ + dd] = vm[dd];
    }
}

// ============================================================
// sparse attention for the u=35 selected queries of each (b,h)
// one block per (b,h)
// ============================================================
__global__ __launch_bounds__(256)
void sparse_attn_kernel(const int* __restrict__ mask)
{
    __shared__ float qs[U_][64];     // also reused as ctx buffer
    __shared__ float Ks[64][68];
    __shared__ float ps[U_][64];
    __shared__ int   sidx[U_];

    const int bh = blockIdx.x, tid = threadIdx.x;
    const int b = bh >> 3, h = bh & 7;
    const float* qp = g_q + (size_t)bh*L_*D_;
    const float* kp = g_k + (size_t)bh*L_*D_;
    const float* vp = g_v + (size_t)bh*L_*D_;
    float* scp = g_sc + (size_t)bh*U_*L_;
    const int* mrow = mask + b*L_;

    if (tid < U_) sidx[tid] = g_idx[bh*U_ + tid];
    __syncthreads();
    for (int i = tid; i < U_*64; i += 256) {
        int u = i >> 6, d = i & 63;
        qs[u][d] = qp[(size_t)sidx[u]*D_ + d];
    }

    // phase 1: scores = (q_red . k) / 8, masked
    for (int kt = 0; kt < L_; kt += 64) {
        __syncthreads();
        for (int i = tid; i < 64*16; i += 256) {
            int row = i >> 4, d4 = (i & 15) << 2;
            *(float4*)&Ks[row][d4] =
                *(const float4*)(kp + (size_t)(kt + row)*D_ + d4);
        }
        __syncthreads();
        for (int p = tid; p < U_*64; p += 256) {
            int u = p >> 6, kk = p & 63;
            float s = 0.f;
#pragma unroll
            for (int d4 = 0; d4 < 64; d4 += 4) {
                float4 a = *(const float4*)&qs[u][d4];
                float4 c = *(const float4*)&Ks[kk][d4];
                s += a.x*c.x + a.y*c.y + a.z*c.z + a.w*c.w;
            }
            int k = kt + kk;
            s *= 0.125f;
            if (mrow[k] == 0) s = -INF_F;
            scp[(size_t)u*L_ + k] = s;
        }
    }
    __syncthreads();

    // phase 2: softmax per selected query row
    const int wid = tid >> 5, lane = tid & 31;
    for (int u = wid; u < U_; u += 8) {
        float mx = -INF_F;
        for (int k = lane; k < L_; k += 32)
            mx = fmaxf(mx, scp[(size_t)u*L_ + k]);
#pragma unroll
        for (int off = 16; off; off >>= 1)
            mx = fmaxf(mx, __shfl_xor_sync(0xffffffffu, mx, off));
        float sm = 0.f;
        for (int k = lane; k < L_; k += 32) {
            float s = scp[(size_t)u*L_ + k];
            sm += (s == -INF_F) ? 0.f : expf(s - mx);
        }
#pragma unroll
        for (int off = 16; off; off >>= 1)
            sm += __shfl_xor_sync(0xffffffffu, sm, off);
        float inv = (sm > 0.f) ? 1.0f / sm : 0.f;
        for (int k = lane; k < L_; k += 32) {
            float s = scp[(size_t)u*L_ + k];
            float pv = (s == -INF_F || mx == -INF_F) ? 0.f : expf(s - mx) * inv;
            scp[(size_t)u*L_ + k] = pv;
        }
    }
    __syncthreads();

    // phase 3: ctx[u, d] = sum_k p[u,k] * v[k,d]
    const int d = tid & 63, part = tid >> 6;
    float acc[U_];
#pragma unroll
    for (int u = 0; u < U_; u++) acc[u] = 0.f;

    for (int kt = 0; kt < L_; kt += 64) {
        __syncthreads();
        for (int i = tid; i < U_*64; i += 256) {
            int u = i >> 6, kk = i & 63;
            ps[u][kk] = scp[(size_t)u*L_ + kt + kk];
        }
        __syncthreads();
        for (int kk = part*16; kk < part*16 + 16; kk++) {
            float v = vp[(size_t)(kt + kk)*D_ + d];
#pragma unroll
            for (int u = 0; u < U_; u++)
                acc[u] += ps[u][kk] * v;
        }
    }

    // reduce across the 4 k-partitions into qs (reused)
    __syncthreads();
    for (int p2 = 0; p2 < 4; p2++) {
        if (part == p2) {
#pragma unroll
            for (int u = 0; u < U_; u++) {
                if (p2 == 0) qs[u][d] = acc[u];
                else         qs[u][d] += acc[u];
            }
        }
        __syncthreads();
    }

    // scatter ctx rows into x2
    float* x2 = g_x2 + (size_t)b*L_*F_ + h*D_;
    for (int i = tid; i < U_*64; i += 256) {
        int u = i >> 6, dd = i & 63;
        x2[(size_t)sidx[u]*F_ + dd] = qs[u][dd];
    }
}

// ============================================================
extern "C" void kernel_launch(void* const* d_in, const int* in_sizes, int n_in,
                              void* d_out, int out_size)
{
    const float* query = (const float*)d_in[0];
    const float* key   = (const float*)d_in[1];
    const float* value = (const float*)d_in[2];
    const int*   mask  = (const int*)  d_in[3];
    const float* Wq = (const float*)d_in[4];
    const float* bq = (const float*)d_in[5];
    const float* Wk = (const float*)d_in[6];
    const float* bk = (const float*)d_in[7];
    const float* Wv = (const float*)d_in[8];
    const float* bv = (const float*)d_in[9];
    const float* Wo = (const float*)d_in[10];
    const float* bo = (const float*)d_in[11];
    float* out = (float*)d_out;

    float *qd, *kd, *vd, *x2d;
    cudaGetSymbolAddress((void**)&qd,  g_q);
    cudaGetSymbolAddress((void**)&kd,  g_k);
    cudaGetSymbolAddress((void**)&vd,  g_v);
    cudaGetSymbolAddress((void**)&x2d, g_x2);

    dim3 gg(F_/64, ML_/64);   // (8, 256)
    gemm_kernel<1><<<gg, 256>>>(query, Wq, bq, qd);
    gemm_kernel<1><<<gg, 256>>>(key,   Wk, bk, kd);
    gemm_kernel<1><<<gg, 256>>>(value, Wv, bv, vd);

    dim3 gm(L_/64, BH_);      // (16, 128)
    qk_m_kernel<<<gm, 256>>>();

    topk_kernel<<<BH_, 256>>>();
    vmean_kernel<<<BH_, 256>>>();
    sparse_attn_kernel<<<BH_, 256>>>(mask);

    gemm_kernel<0><<<gg, 256>>>(x2d, Wo, bo, out);
}

// round 2
// speedup vs baseline: 1.0652x; 1.0652x over previous
#include <cuda_runtime.h>
#include <cstdint>

typedef unsigned long long u64;

#define B_  16
#define L_  1024
#define F_  512
#define H_  8
#define D_  64
#define U_  35
#define BH_ (B_*H_)     // 128
#define ML_ (B_*L_)     // 16384

#define INF_F __int_as_float(0x7f800000)

// -------- device scratch (no allocations allowed) --------
__device__ float g_q[(size_t)BH_*L_*D_];     // (B,H,L,D)
__device__ float g_k[(size_t)BH_*L_*D_];
__device__ float g_v[(size_t)BH_*L_*D_];
__device__ float g_M[(size_t)BH_*L_];
__device__ int   g_idx[BH_*U_];
__device__ float g_x2[(size_t)ML_*F_];       // context in (B,L,F) layout
__device__ float g_sc[(size_t)BH_*U_*L_];    // sparse scores / probs

// -------- f32x2 helpers --------
__device__ __forceinline__ void fma2(u64 &acc, u64 a, u64 b) {
    asm("fma.rn.f32x2 %0, %1, %2, %0;" : "+l"(acc) : "l"(a), "l"(b));
}
__device__ __forceinline__ u64 dup2(float v) {
    u64 r; asm("mov.b64 %0, {%1, %1};" : "=l"(r) : "f"(v)); return r;
}
__device__ __forceinline__ float2 unpk(u64 v) {
    float2 r; asm("mov.b64 {%0, %1}, %2;" : "=f"(r.x), "=f"(r.y) : "l"(v)); return r;
}

// ============================================================
// GEMM: C[M,N] = X[M,K] @ W[N,K]^T + bias ; M=16384, N=K=512
// 128x128 tile, 256 threads, 8x8 micro via f32x2 row-pairs.
// As[k][mp*2+half] = X[m0+mp+half*64][k]  (interleaved row-pairs)
// Bs[k][n]         = W[n0+n][k]
// ATTN=1: write out[((b*H+h)*L+l)*D+d], else row-major [m*F+n]
// ============================================================
template<int ATTN>
__global__ __launch_bounds__(256, 1)
void gemm2_kernel(const float* __restrict__ X,
                  const float* __restrict__ W,
                  const float* __restrict__ bias,
                  float* __restrict__ out)
{
    __shared__ __align__(16) float As[32][130];
    __shared__ __align__(16) float Bs[32][130];
    const int tid = threadIdx.x;
    const int tx = tid & 15, ty = tid >> 4;
    const int m0 = blockIdx.y * 128, n0 = blockIdx.x * 128;

    u64 acc[4][8];
#pragma unroll
    for (int i = 0; i < 4; i++)
#pragma unroll
        for (int j = 0; j < 8; j++) acc[i][j] = 0ULL;

    // prefetch first k-chunk into registers
    float4 ra[4], rb[4];
#pragma unroll
    for (int i = 0; i < 4; i++) {
        int idx = tid + i*256;
        int r = idx >> 3, kc = (idx & 7) << 2;
        ra[i] = *(const float4*)(X + (size_t)(m0 + r)*F_ + kc);
        rb[i] = *(const float4*)(W + (size_t)(n0 + r)*F_ + kc);
    }

    for (int kt = 0; kt < F_; kt += 32) {
        __syncthreads();
#pragma unroll
        for (int i = 0; i < 4; i++) {
            int idx = tid + i*256;
            int r = idx >> 3, kc = (idx & 7) << 2;
            int mo = ((r & 63) << 1) | (r >> 6);
            As[kc+0][mo] = ra[i].x; As[kc+1][mo] = ra[i].y;
            As[kc+2][mo] = ra[i].z; As[kc+3][mo] = ra[i].w;
            Bs[kc+0][r] = rb[i].x;  Bs[kc+1][r] = rb[i].y;
            Bs[kc+2][r] = rb[i].z;  Bs[kc+3][r] = rb[i].w;
        }
        __syncthreads();
        if (kt + 32 < F_) {
#pragma unroll
            for (int i = 0; i < 4; i++) {
                int idx = tid + i*256;
                int r = idx >> 3, kc = (idx & 7) << 2;
                ra[i] = *(const float4*)(X + (size_t)(m0 + r)*F_ + kt + 32 + kc);
                rb[i] = *(const float4*)(W + (size_t)(n0 + r)*F_ + kt + 32 + kc);
            }
        }
#pragma unroll 16
        for (int kk = 0; kk < 32; kk++) {
            u64 av[4];
#pragma unroll
            for (int i = 0; i < 4; i++)
                av[i] = *(const u64*)&As[kk][(ty<<3) + (i<<1)];
            u64 bv[8];
#pragma unroll
            for (int j2 = 0; j2 < 4; j2++) {
                float2 b2 = *(const float2*)&Bs[kk][(tx<<3) + (j2<<1)];
                bv[j2*2]   = dup2(b2.x);
                bv[j2*2+1] = dup2(b2.y);
            }
#pragma unroll
            for (int i = 0; i < 4; i++)
#pragma unroll
                for (int j = 0; j < 8; j++)
                    fma2(acc[i][j], av[i], bv[j]);
        }
    }

    const int nb = n0 + (tx << 3);
    float bb[8];
#pragma unroll
    for (int j = 0; j < 8; j++) bb[j] = bias[nb + j];

#pragma unroll
    for (int i = 0; i < 4; i++) {
        float lo[8], hi[8];
#pragma unroll
        for (int j = 0; j < 8; j++) {
            float2 t = unpk(acc[i][j]);
            lo[j] = t.x + bb[j];
            hi[j] = t.y + bb[j];
        }
        {   // lo row
            int m = m0 + (ty << 2) + i;
            float* p;
            if (ATTN) {
                int b = m >> 10, l = m & (L_-1);
                int h = nb >> 6, d = nb & (D_-1);
                p = out + ((size_t)(b*H_ + h)*L_ + l)*D_ + d;
            } else {
                p = out + (size_t)m*F_ + nb;
            }
            *(float4*)p     = make_float4(lo[0], lo[1], lo[2], lo[3]);
            *(float4*)(p+4) = make_float4(lo[4], lo[5], lo[6], lo[7]);
        }
        {   // hi row (+64)
            int m = m0 + (ty << 2) + i + 64;
            float* p;
            if (ATTN) {
                int b = m >> 10, l = m & (L_-1);
                int h = nb >> 6, d = nb & (D_-1);
                p = out + ((size_t)(b*H_ + h)*L_ + l)*D_ + d;
            } else {
                p = out + (size_t)m*F_ + nb;
            }
            *(float4*)p     = make_float4(hi[0], hi[1], hi[2], hi[3]);
            *(float4*)(p+4) = make_float4(hi[4], hi[5], hi[6], hi[7]);
        }
    }
}

// ============================================================
// M[b,h,q] = max_k(q.k) - mean_k(q.k) ; fused QK + row reduce
// 128q x 128k tiles, f32x2, Q resident (all 64 d), K chunked 16d.
// grid: (L/128, BH), block 256
// ============================================================
__global__ __launch_bounds__(256, 1)
void qk_m2_kernel()
{
    __shared__ __align__(16) float Qs[64][130];   // [d][qp*2+half]
    __shared__ __align__(16) float Ks[16][130];   // [d][k]
    const int tid = threadIdx.x;
    const int tx = tid & 15, ty = tid >> 4;
    const int bh = blockIdx.y;
    const int q0 = blockIdx.x * 128;
    const float* qp = g_q + (size_t)bh*L_*D_;
    const float* kp = g_k + (size_t)bh*L_*D_;

    // stage Q tile once (128 q x 64 d), transposed + row-pair interleaved
#pragma unroll
    for (int i = 0; i < 8; i++) {
        int idx = tid + i*256;
        int q = idx >> 4, dc = (idx & 15) << 2;
        float4 v = *(const float4*)(qp + (size_t)(q0 + q)*D_ + dc);
        int qo = ((q & 63) << 1) | (q >> 6);
        Qs[dc+0][qo] = v.x; Qs[dc+1][qo] = v.y;
        Qs[dc+2][qo] = v.z; Qs[dc+3][qo] = v.w;
    }

    float rmax[8], rsum[8];
#pragma unroll
    for (int r = 0; r < 8; r++) { rmax[r] = -INF_F; rsum[r] = 0.f; }

    u64 acc[4][8];
    float4 rk[2];
    // prefetch chunk 0 (ktile 0, d0=0)
#pragma unroll
    for (int i = 0; i < 2; i++) {
        int idx = tid + i*256;
        int k = idx >> 2, dc = (idx & 3) << 2;
        rk[i] = *(const float4*)(kp + (size_t)k*D_ + dc);
    }

    // 32 chunks = 8 k-tiles x 4 d-chunks of 16
    for (int c = 0; c < 32; c++) {
        if ((c & 3) == 0) {
#pragma unroll
            for (int i = 0; i < 4; i++)
#pragma unroll
                for (int j = 0; j < 8; j++) acc[i][j] = 0ULL;
        }
        __syncthreads();
#pragma unroll
        for (int i = 0; i < 2; i++) {
            int idx = tid + i*256;
            int k = idx >> 2, dc = (idx & 3) << 2;
            int ko = ((k & 63) << 1) | (k >> 6);
            Ks[dc+0][ko] = rk[i].x; Ks[dc+1][ko] = rk[i].y;
            Ks[dc+2][ko] = rk[i].z; Ks[dc+3][ko] = rk[i].w;
        }
        __syncthreads();
        if (c + 1 < 32) {
            int ktn = ((c+1) >> 2) * 128;
            int d0n = ((c+1) & 3) * 16;
#pragma unroll
            for (int i = 0; i < 2; i++) {
                int idx = tid + i*256;
                int k = idx >> 2, dc = (idx & 3) << 2;
                rk[i] = *(const float4*)(kp + (size_t)(ktn + k)*D_ + d0n + dc);
            }
        }
        const int d0 = (c & 3) * 16;
#pragma unroll
        for (int dd = 0; dd < 16; dd++) {
            u64 av[4];
#pragma unroll
            for (int i = 0; i < 4; i++)
                av[i] = *(const u64*)&Qs[d0+dd][(ty<<3) + (i<<1)];
            u64 bv[8];
#pragma unroll
            for (int j2 = 0; j2 < 4; j2++) {
                float2 b2 = *(const float2*)&Ks[dd][(tx<<3) + (j2<<1)];
                bv[j2*2]   = dup2(b2.x);
                bv[j2*2+1] = dup2(b2.y);
            }
#pragma unroll
            for (int i = 0; i < 4; i++)
#pragma unroll
                for (int j = 0; j < 8; j++)
                    fma2(acc[i][j], av[i], bv[j]);
        }
        if ((c & 3) == 3) {
            // scores for this k-tile complete: fold into running max/sum
#pragma unroll
            for (int i = 0; i < 4; i++) {
                float mLo = -INF_F, mHi = -INF_F, sLo = 0.f, sHi = 0.f;
#pragma unroll
                for (int j = 0; j < 8; j++) {
                    float2 t = unpk(acc[i][j]);
                    mLo = fmaxf(mLo, t.x); sLo += t.x;
                    mHi = fmaxf(mHi, t.y); sHi += t.y;
                }
                rmax[i]   = fmaxf(rmax[i],   mLo); rsum[i]   += sLo;
                rmax[i+4] = fmaxf(rmax[i+4], mHi); rsum[i+4] += sHi;
            }
        }
    }

    // reduce across the 16 tx lanes (within half-warps)
#pragma unroll
    for (int r = 0; r < 8; r++) {
        float m = rmax[r], s = rsum[r];
#pragma unroll
        for (int off = 8; off; off >>= 1) {
            m = fmaxf(m, __shfl_xor_sync(0xffffffffu, m, off));
            s += __shfl_xor_sync(0xffffffffu, s, off);
        }
        rmax[r] = m; rsum[r] = s;
    }
    if (tx == 0) {
#pragma unroll
        for (int r = 0; r < 8; r++) {
            int row = q0 + (ty << 2) + (r & 3) + ((r >> 2) << 6);
            g_M[(size_t)bh*L_ + row] = rmax[r] - rsum[r] * (1.0f/L_);
        }
    }
}

// ============================================================
// top-35 indices per (b,h) via iterative argmax (tie: lowest idx)
// ============================================================
__global__ __launch_bounds__(256)
void topk_kernel()
{
    __shared__ float sv[L_];
    __shared__ float rv[256];
    __shared__ int   ri[256];
    const int bh = blockIdx.x, tid = threadIdx.x;
    for (int i = tid; i < L_; i += 256) sv[i] = g_M[(size_t)bh*L_ + i];
    __syncthreads();

    for (int it = 0; it < U_; it++) {
        float bvv = -INF_F; int bii = 0;
#pragma unroll
        for (int j = 0; j < 4; j++) {
            int k = tid*4 + j;
            float v = sv[k];
            if (v > bvv) { bvv = v; bii = k; }
        }
        rv[tid] = bvv; ri[tid] = bii;
        __syncthreads();
        for (int s = 128; s; s >>= 1) {
            if (tid < s) {
                float v2 = rv[tid + s]; int i2 = ri[tid + s];
                if (v2 > rv[tid] || (v2 == rv[tid] && i2 < ri[tid])) {
                    rv[tid] = v2; ri[tid] = i2;
                }
            }
            __syncthreads();
        }
        if (tid == 0) {
            g_idx[bh*U_ + it] = ri[0];
            sv[ri[0]] = -INF_F;
        }
        __syncthreads();
    }
}

// ============================================================
// vmean broadcast: x2[b, l, h*64+d] = mean_l v[b,h,l,d]
// ============================================================
__global__ __launch_bounds__(256)
void vmean_kernel()
{
    const int bh = blockIdx.x, tid = threadIdx.x;
    const int d = tid & 63, part = tid >> 6;
    const float* vp = g_v + (size_t)bh*L_*D_;
    float acc = 0.f;
    for (int l = part*256; l < part*256 + 256; l++)
        acc += vp[(size_t)l*D_ + d];

    __shared__ float red[4][64];
    __shared__ float vm[64];
    red[part][d] = acc;
    __syncthreads();
    if (tid < 64)
        vm[tid] = (red[0][tid] + red[1][tid] + red[2][tid] + red[3][tid]) * (1.0f / L_);
    __syncthreads();

    const int b = bh >> 3, h = bh & 7;
    float* x2 = g_x2 + (size_t)b*L_*F_ + h*D_;
    for (int i = tid; i < L_*D_; i += 256) {
        int l = i >> 6, dd = i & 63;
        x2[(size_t)l*F_ + dd] = vm[dd];
    }
}

// ============================================================
// sparse attention for the u=35 selected queries of each (b,h)
// one block per (b,h)
// ============================================================
__global__ __launch_bounds__(256)
void sparse_attn_kernel(const int* __restrict__ mask)
{
    __shared__ float qs[U_][64];     // also reused as ctx buffer
    __shared__ float Ks[64][68];
    __shared__ float ps[U_][64];
    __shared__ int   sidx[U_];

    const int bh = blockIdx.x, tid = threadIdx.x;
    const int b = bh >> 3, h = bh & 7;
    const float* qp = g_q + (size_t)bh*L_*D_;
    const float* kp = g_k + (size_t)bh*L_*D_;
    const float* vp = g_v + (size_t)bh*L_*D_;
    float* scp = g_sc + (size_t)bh*U_*L_;
    const int* mrow = mask + b*L_;

    if (tid < U_) sidx[tid] = g_idx[bh*U_ + tid];
    __syncthreads();
    for (int i = tid; i < U_*64; i += 256) {
        int u = i >> 6, d = i & 63;
        qs[u][d] = qp[(size_t)sidx[u]*D_ + d];
    }

    // phase 1: scores = (q_red . k) / 8, masked
    for (int kt = 0; kt < L_; kt += 64) {
        __syncthreads();
        for (int i = tid; i < 64*16; i += 256) {
            int row = i >> 4, d4 = (i & 15) << 2;
            *(float4*)&Ks[row][d4] =
                *(const float4*)(kp + (size_t)(kt + row)*D_ + d4);
        }
        __syncthreads();
        for (int p = tid; p < U_*64; p += 256) {
            int u = p >> 6, kk = p & 63;
            float s = 0.f;
#pragma unroll
            for (int d4 = 0; d4 < 64; d4 += 4) {
                float4 a = *(const float4*)&qs[u][d4];
                float4 c = *(const float4*)&Ks[kk][d4];
                s += a.x*c.x + a.y*c.y + a.z*c.z + a.w*c.w;
            }
            int k = kt + kk;
            s *= 0.125f;
            if (mrow[k] == 0) s = -INF_F;
            scp[(size_t)u*L_ + k] = s;
        }
    }
    __syncthreads();

    // phase 2: softmax per selected query row
    const int wid = tid >> 5, lane = tid & 31;
    for (int u = wid; u < U_; u += 8) {
        float mx = -INF_F;
        for (int k = lane; k < L_; k += 32)
            mx = fmaxf(mx, scp[(size_t)u*L_ + k]);
#pragma unroll
        for (int off = 16; off; off >>= 1)
            mx = fmaxf(mx, __shfl_xor_sync(0xffffffffu, mx, off));
        float sm = 0.f;
        for (int k = lane; k < L_; k += 32) {
            float s = scp[(size_t)u*L_ + k];
            sm += (s == -INF_F) ? 0.f : expf(s - mx);
        }
#pragma unroll
        for (int off = 16; off; off >>= 1)
            sm += __shfl_xor_sync(0xffffffffu, sm, off);
        float inv = (sm > 0.f) ? 1.0f / sm : 0.f;
        for (int k = lane; k < L_; k += 32) {
            float s = scp[(size_t)u*L_ + k];
            float pv = (s == -INF_F || mx == -INF_F) ? 0.f : expf(s - mx) * inv;
            scp[(size_t)u*L_ + k] = pv;
        }
    }
    __syncthreads();

    // phase 3: ctx[u, d] = sum_k p[u,k] * v[k,d]
    const int d = tid & 63, part = tid >> 6;
    float acc[U_];
#pragma unroll
    for (int u = 0; u < U_; u++) acc[u] = 0.f;

    for (int kt = 0; kt < L_; kt += 64) {
        __syncthreads();
        for (int i = tid; i < U_*64; i += 256) {
            int u = i >> 6, kk = i & 63;
            ps[u][kk] = scp[(size_t)u*L_ + kt + kk];
        }
        __syncthreads();
        for (int kk = part*16; kk < part*16 + 16; kk++) {
            float v = vp[(size_t)(kt + kk)*D_ + d];
#pragma unroll
            for (int u = 0; u < U_; u++)
                acc[u] += ps[u][kk] * v;
        }
    }

    // reduce across the 4 k-partitions into qs (reused)
    __syncthreads();
    for (int p2 = 0; p2 < 4; p2++) {
        if (part == p2) {
#pragma unroll
            for (int u = 0; u < U_; u++) {
                if (p2 == 0) qs[u][d] = acc[u];
                else         qs[u][d] += acc[u];
            }
        }
        __syncthreads();
    }

    // scatter ctx rows into x2
    float* x2 = g_x2 + (size_t)b*L_*F_ + h*D_;
    for (int i = tid; i < U_*64; i += 256) {
        int u = i >> 6, dd = i & 63;
        x2[(size_t)sidx[u]*F_ + dd] = qs[u][dd];
    }
}

// ============================================================
extern "C" void kernel_launch(void* const* d_in, const int* in_sizes, int n_in,
                              void* d_out, int out_size)
{
    const float* query = (const float*)d_in[0];
    const float* key   = (const float*)d_in[1];
    const float* value = (const float*)d_in[2];
    const int*   mask  = (const int*)  d_in[3];
    const float* Wq = (const float*)d_in[4];
    const float* bq = (const float*)d_in[5];
    const float* Wk = (const float*)d_in[6];
    const float* bk = (const float*)d_in[7];
    const float* Wv = (const float*)d_in[8];
    const float* bv = (const float*)d_in[9];
    const float* Wo = (const float*)d_in[10];
    const float* bo = (const float*)d_in[11];
    float* out = (float*)d_out;

    float *qd, *kd, *vd, *x2d;
    cudaGetSymbolAddress((void**)&qd,  g_q);
    cudaGetSymbolAddress((void**)&kd,  g_k);
    cudaGetSymbolAddress((void**)&vd,  g_v);
    cudaGetSymbolAddress((void**)&x2d, g_x2);

    dim3 gg(F_/128, ML_/128);   // (4, 128)
    gemm2_kernel<1><<<gg, 256>>>(query, Wq, bq, qd);
    gemm2_kernel<1><<<gg, 256>>>(key,   Wk, bk, kd);
    gemm2_kernel<1><<<gg, 256>>>(value, Wv, bv, vd);

    dim3 gm(L_/128, BH_);       // (8, 128)
    qk_m2_kernel<<<gm, 256>>>();

    topk_kernel<<<BH_, 256>>>();
    vmean_kernel<<<BH_, 256>>>();
    sparse_attn_kernel<<<BH_, 256>>>(mask);

    gemm2_kernel<0><<<gg, 256>>>(x2d, Wo, bo, out);
}

// round 3
// speedup vs baseline: 1.2950x; 1.2157x over previous
#include <cuda_runtime.h>
#include <cstdint>

typedef unsigned long long u64;

#define B_  16
#define L_  1024
#define F_  512
#define H_  8
#define D_  64
#define U_  35
#define BH_ (B_*H_)     // 128
#define ML_ (B_*L_)     // 16384

#define INF_F __int_as_float(0x7f800000)

// -------- device scratch (no allocations allowed) --------
__device__ float g_q[(size_t)BH_*L_*D_];     // (B,H,L,D)
__device__ float g_k[(size_t)BH_*L_*D_];
__device__ float g_v[(size_t)BH_*L_*D_];
__device__ float g_M[(size_t)BH_*L_];
__device__ int   g_idx[BH_*U_];
__device__ float g_x2[(size_t)ML_*F_];       // context rows (only selected rows valid)
__device__ float g_sc[(size_t)BH_*U_*L_];    // sparse scores / probs
__device__ float g_vm[BH_*D_];               // per-(b,h) V mean
__device__ float g_om[B_*F_];                // per-b mean-output row
__device__ int   g_flag[B_*L_];
__device__ int   g_cnt[B_];
__device__ int   g_rows[B_*L_];

// -------- f32x2 helpers --------
__device__ __forceinline__ void fma2(u64 &acc, u64 a, u64 b) {
    asm("fma.rn.f32x2 %0, %1, %2, %0;" : "+l"(acc) : "l"(a), "l"(b));
}
__device__ __forceinline__ u64 dup2(float v) {
    u64 r; asm("mov.b64 %0, {%1, %1};" : "=l"(r) : "f"(v)); return r;
}
__device__ __forceinline__ float2 unpk(u64 v) {
    float2 r; asm("mov.b64 {%0, %1}, %2;" : "=f"(r.x), "=f"(r.y) : "l"(v)); return r;
}

// ============================================================
// GEMM: C[M,N] = X[M,K] @ W[N,K]^T + bias ; M=16384, N=K=512
// 128x128 tile, 256 threads, 8x8 micro (f32x2 row-pairs),
// double-buffered smem, one sync per 16-k chunk, 2 blocks/SM.
// ============================================================
template<int ATTN>
__global__ __launch_bounds__(256, 2)
void gemm3_kernel(const float* __restrict__ X,
                  const float* __restrict__ W,
                  const float* __restrict__ bias,
                  float* __restrict__ out)
{
    __shared__ __align__(16) float As[2][16][132];
    __shared__ __align__(16) float Bs[2][16][132];
    const int tid = threadIdx.x;
    const int tx = tid & 15, ty = tid >> 4;
    const int m0 = blockIdx.y * 128, n0 = blockIdx.x * 128;
    const int r  = tid >> 2;            // 0..63
    const int kc = (tid & 3) << 2;      // 0,4,8,12
    const int mo = r << 1;

    u64 acc[4][8];
#pragma unroll
    for (int i = 0; i < 4; i++)
#pragma unroll
        for (int j = 0; j < 8; j++) acc[i][j] = 0ULL;

    float4 ra0, ra1, rb0, rb1;
    ra0 = *(const float4*)(X + (size_t)(m0 + r)*F_ + kc);
    ra1 = *(const float4*)(X + (size_t)(m0 + r + 64)*F_ + kc);
    rb0 = *(const float4*)(W + (size_t)(n0 + r)*F_ + kc);
    rb1 = *(const float4*)(W + (size_t)(n0 + r + 64)*F_ + kc);

#define GSTORE(bsel) do { \
    As[bsel][kc+0][mo]   = ra0.x; As[bsel][kc+1][mo]   = ra0.y; \
    As[bsel][kc+2][mo]   = ra0.z; As[bsel][kc+3][mo]   = ra0.w; \
    As[bsel][kc+0][mo+1] = ra1.x; As[bsel][kc+1][mo+1] = ra1.y; \
    As[bsel][kc+2][mo+1] = ra1.z; As[bsel][kc+3][mo+1] = ra1.w; \
    Bs[bsel][kc+0][r]    = rb0.x; Bs[bsel][kc+1][r]    = rb0.y; \
    Bs[bsel][kc+2][r]    = rb0.z; Bs[bsel][kc+3][r]    = rb0.w; \
    Bs[bsel][kc+0][r+64] = rb1.x; Bs[bsel][kc+1][r+64] = rb1.y; \
    Bs[bsel][kc+2][r+64] = rb1.z; Bs[bsel][kc+3][r+64] = rb1.w; } while(0)

    GSTORE(0);
    __syncthreads();

    for (int c = 0; c < 32; c++) {
        if (c < 31) {
            int kb = (c + 1) << 4;
            ra0 = *(const float4*)(X + (size_t)(m0 + r)*F_ + kb + kc);
            ra1 = *(const float4*)(X + (size_t)(m0 + r + 64)*F_ + kb + kc);
            rb0 = *(const float4*)(W + (size_t)(n0 + r)*F_ + kb + kc);
            rb1 = *(const float4*)(W + (size_t)(n0 + r + 64)*F_ + kb + kc);
        }
        const int bsel = c & 1;
#pragma unroll
        for (int kk = 0; kk < 16; kk++) {
            ulonglong2 a01 = *(const ulonglong2*)&As[bsel][kk][ty << 3];
            ulonglong2 a23 = *(const ulonglong2*)&As[bsel][kk][(ty << 3) + 4];
            float4 b0 = *(const float4*)&Bs[bsel][kk][tx << 3];
            float4 b1 = *(const float4*)&Bs[bsel][kk][(tx << 3) + 4];
            u64 av[4] = {a01.x, a01.y, a23.x, a23.y};
            u64 bv[8] = {dup2(b0.x), dup2(b0.y), dup2(b0.z), dup2(b0.w),
                         dup2(b1.x), dup2(b1.y), dup2(b1.z), dup2(b1.w)};
#pragma unroll
            for (int i = 0; i < 4; i++)
#pragma unroll
                for (int j = 0; j < 8; j++)
                    fma2(acc[i][j], av[i], bv[j]);
        }
        if (c < 31) GSTORE((c + 1) & 1);
        __syncthreads();
    }
#undef GSTORE

    const int nb = n0 + (tx << 3);
    float bb[8];
#pragma unroll
    for (int j = 0; j < 8; j++) bb[j] = bias[nb + j];

#pragma unroll
    for (int i = 0; i < 4; i++) {
        float lo[8], hi[8];
#pragma unroll
        for (int j = 0; j < 8; j++) {
            float2 t = unpk(acc[i][j]);
            lo[j] = t.x + bb[j];
            hi[j] = t.y + bb[j];
        }
        {
            int m = m0 + (ty << 2) + i;
            float* p;
            if (ATTN) {
                int b = m >> 10, l = m & (L_-1);
                int h = nb >> 6, d = nb & (D_-1);
                p = out + ((size_t)(b*H_ + h)*L_ + l)*D_ + d;
            } else {
                p = out + (size_t)m*F_ + nb;
            }
            *(float4*)p     = make_float4(lo[0], lo[1], lo[2], lo[3]);
            *(float4*)(p+4) = make_float4(lo[4], lo[5], lo[6], lo[7]);
        }
        {
            int m = m0 + (ty << 2) + i + 64;
            float* p;
            if (ATTN) {
                int b = m >> 10, l = m & (L_-1);
                int h = nb >> 6, d = nb & (D_-1);
                p = out + ((size_t)(b*H_ + h)*L_ + l)*D_ + d;
            } else {
                p = out + (size_t)m*F_ + nb;
            }
            *(float4*)p     = make_float4(hi[0], hi[1], hi[2], hi[3]);
            *(float4*)(p+4) = make_float4(hi[4], hi[5], hi[6], hi[7]);
        }
    }
}

// ============================================================
// M[b,h,q] = max_k(q.k) - mean_k(q.k); Q tile resident, K
// double-buffered in 8-d chunks, one sync per chunk, 2 blk/SM.
// grid: (L/128, BH), block 256
// ============================================================
__global__ __launch_bounds__(256, 2)
void qk_m3_kernel()
{
    __shared__ float Qs[64][130];        // [d][q-pair-interleaved]
    __shared__ float Ks[2][8][130];      // [d-chunk][k]
    const int tid = threadIdx.x;
    const int tx = tid & 15, ty = tid >> 4;
    const int bh = blockIdx.y;
    const int q0 = blockIdx.x * 128;
    const float* qp = g_q + (size_t)bh*L_*D_;
    const float* kp = g_k + (size_t)bh*L_*D_;

#pragma unroll
    for (int i = 0; i < 8; i++) {
        int idx = tid + i*256;
        int q = idx >> 4, dc = (idx & 15) << 2;
        float4 v = *(const float4*)(qp + (size_t)(q0 + q)*D_ + dc);
        int qo = ((q & 63) << 1) | (q >> 6);
        Qs[dc+0][qo] = v.x; Qs[dc+1][qo] = v.y;
        Qs[dc+2][qo] = v.z; Qs[dc+3][qo] = v.w;
    }

    const int kr  = tid >> 1;            // 0..127
    const int dc2 = (tid & 1) << 2;      // 0 or 4

    float rmax[8], rsum[8];
#pragma unroll
    for (int r2 = 0; r2 < 8; r2++) { rmax[r2] = -INF_F; rsum[r2] = 0.f; }
    u64 acc[4][8];

    float4 rk = *(const float4*)(kp + (size_t)kr*D_ + dc2);
#define KST(bsel) do { \
    Ks[bsel][dc2+0][kr] = rk.x; Ks[bsel][dc2+1][kr] = rk.y; \
    Ks[bsel][dc2+2][kr] = rk.z; Ks[bsel][dc2+3][kr] = rk.w; } while(0)
    KST(0);
    __syncthreads();

    // 64 chunks = 8 k-tiles(128) x 8 d-chunks(8)
    for (int c = 0; c < 64; c++) {
        if ((c & 7) == 0) {
#pragma unroll
            for (int i = 0; i < 4; i++)
#pragma unroll
                for (int j = 0; j < 8; j++) acc[i][j] = 0ULL;
        }
        if (c < 63) {
            int ktn = ((c+1) >> 3) << 7;
            int d0n = ((c+1) & 7) << 3;
            rk = *(const float4*)(kp + (size_t)(ktn + kr)*D_ + d0n + dc2);
        }
        const int bsel = c & 1;
        const int d0 = (c & 7) << 3;
#pragma unroll
        for (int dd = 0; dd < 8; dd++) {
            const float* qrow = &Qs[d0+dd][ty << 3];
            u64 av[4];
            av[0] = *(const u64*)(qrow);
            av[1] = *(const u64*)(qrow + 2);
            av[2] = *(const u64*)(qrow + 4);
            av[3] = *(const u64*)(qrow + 6);
            const float* krow = &Ks[bsel][dd][tx << 3];
            u64 bv[8];
#pragma unroll
            for (int j2 = 0; j2 < 4; j2++) {
                float2 b2 = *(const float2*)(krow + (j2 << 1));
                bv[j2*2]   = dup2(b2.x);
                bv[j2*2+1] = dup2(b2.y);
            }
#pragma unroll
            for (int i = 0; i < 4; i++)
#pragma unroll
                for (int j = 0; j < 8; j++)
                    fma2(acc[i][j], av[i], bv[j]);
        }
        if ((c & 7) == 7) {
#pragma unroll
            for (int i = 0; i < 4; i++) {
                float mLo = -INF_F, mHi = -INF_F, sLo = 0.f, sHi = 0.f;
#pragma unroll
                for (int j = 0; j < 8; j++) {
                    float2 t2 = unpk(acc[i][j]);
                    mLo = fmaxf(mLo, t2.x); sLo += t2.x;
                    mHi = fmaxf(mHi, t2.y); sHi += t2.y;
                }
                rmax[i]   = fmaxf(rmax[i],   mLo); rsum[i]   += sLo;
                rmax[i+4] = fmaxf(rmax[i+4], mHi); rsum[i+4] += sHi;
            }
        }
        if (c < 63) KST((c+1) & 1);
        __syncthreads();
    }
#undef KST

#pragma unroll
    for (int r2 = 0; r2 < 8; r2++) {
        float m = rmax[r2], s = rsum[r2];
#pragma unroll
        for (int off = 8; off; off >>= 1) {
            m = fmaxf(m, __shfl_xor_sync(0xffffffffu, m, off));
            s += __shfl_xor_sync(0xffffffffu, s, off);
        }
        rmax[r2] = m; rsum[r2] = s;
    }
    if (tx == 0) {
#pragma unroll
        for (int r2 = 0; r2 < 8; r2++) {
            int row = q0 + (ty << 2) + (r2 & 3) + ((r2 >> 2) << 6);
            g_M[(size_t)bh*L_ + row] = rmax[r2] - rsum[r2] * (1.0f/L_);
        }
    }
}

// ============================================================
// warp-private top-35 (one warp per (b,h), values in registers)
// ============================================================
__global__ __launch_bounds__(256)
void topk_warp_kernel()
{
    const int warp = threadIdx.x >> 5, lane = threadIdx.x & 31;
    const int bh = blockIdx.x * 8 + warp;
    const float* Mp = g_M + (size_t)bh*L_;
    float v[32];
#pragma unroll
    for (int j = 0; j < 32; j++) v[j] = Mp[j*32 + lane];

    for (int it = 0; it < U_; it++) {
        float bv = v[0]; int bj = 0;
#pragma unroll
        for (int j = 1; j < 32; j++)
            if (v[j] > bv) { bv = v[j]; bj = j; }
        int bk = bj*32 + lane;
#pragma unroll
        for (int off = 16; off; off >>= 1) {
            float ov = __shfl_xor_sync(0xffffffffu, bv, off);
            int   ok = __shfl_xor_sync(0xffffffffu, bk, off);
            if (ov > bv || (ov == bv && ok < bk)) { bv = ov; bk = ok; }
        }
        if (lane == 0) g_idx[bh*U_ + it] = bk;
        int cj = bk >> 5;
        bool mine = ((bk & 31) == lane);
#pragma unroll
        for (int j = 0; j < 32; j++)
            if (mine && j == cj) v[j] = -INF_F;
    }
}

// ============================================================
// vm[b,h,d] = mean over l of v
// ============================================================
__global__ __launch_bounds__(256)
void vmean_kernel()
{
    const int bh = blockIdx.x, tid = threadIdx.x;
    const int d = tid & 63, part = tid >> 6;
    const float* vp = g_v + (size_t)bh*L_*D_;
    float acc = 0.f;
    for (int l = part*256; l < part*256 + 256; l++)
        acc += vp[(size_t)l*D_ + d];
    __shared__ float red[4][64];
    red[part][d] = acc;
    __syncthreads();
    if (tid < 64)
        g_vm[bh*64 + tid] =
            (red[0][tid] + red[1][tid] + red[2][tid] + red[3][tid]) * (1.0f/L_);
}

// ============================================================
// flags/counters reset + selected-row compaction per batch
// ============================================================
__global__ void zero_kernel()
{
    int t = blockIdx.x*256 + threadIdx.x;
    if (t < B_*L_) g_flag[t] = 0;
    if (t < B_)    g_cnt[t]  = 0;
}

__global__ void compact_kernel()
{
    int t = blockIdx.x*256 + threadIdx.x;
    if (t >= BH_*U_) return;
    int bh = t / U_;
    int b  = bh >> 3;
    int row = g_idx[t];
    if (atomicExch(&g_flag[b*L_ + row], 1) == 0) {
        int p = atomicAdd(&g_cnt[b], 1);
        g_rows[b*L_ + p] = row;
    }
}

// ============================================================
// init x2 rows in the selected union with vm-concat
// grid (B_, 3)
// ============================================================
__global__ __launch_bounds__(256)
void x2init_kernel()
{
    const int b = blockIdx.x, t = blockIdx.y, tid = threadIdx.x;
    __shared__ float vms[F_];
    for (int f = tid; f < F_; f += 256)
        vms[f] = g_vm[(b*H_ + (f >> 6))*64 + (f & 63)];
    __syncthreads();
    const int cnt = g_cnt[b];
    int hiR = t*128 + 128; if (hiR > cnt) hiR = cnt;
    for (int ri = t*128; ri < hiR; ri++) {
        int l = g_rows[b*L_ + ri];
        float* p = g_x2 + ((size_t)b*L_ + l)*F_;
        p[tid]       = vms[tid];
        p[tid + 256] = vms[tid + 256];
    }
}

// ============================================================
// sparse scores: grid (BH_, 8); block does 35u x 128k
// ============================================================
__global__ __launch_bounds__(256)
void sp_scores_kernel(const int* __restrict__ mask)
{
    __shared__ float qs[U_][64];
    __shared__ float Ks[128][68];
    __shared__ int   sidx[U_];
    const int bh = blockIdx.x, tid = threadIdx.x;
    const int b = bh >> 3;
    const int kt0 = blockIdx.y << 7;
    const float* qp = g_q + (size_t)bh*L_*D_;
    const float* kp = g_k + (size_t)bh*L_*D_;
    float* scp = g_sc + (size_t)bh*U_*L_;
    const int* mrow = mask + b*L_;

    if (tid < U_) sidx[tid] = g_idx[bh*U_ + tid];
    __syncthreads();
    for (int i = tid; i < U_*16; i += 256) {
        int u = i >> 4, dc = (i & 15) << 2;
        *(float4*)&qs[u][dc] = *(const float4*)(qp + (size_t)sidx[u]*D_ + dc);
    }
    for (int i = tid; i < 128*16; i += 256) {
        int k = i >> 4, dc = (i & 15) << 2;
        *(float4*)&Ks[k][dc] = *(const float4*)(kp + (size_t)(kt0 + k)*D_ + dc);
    }
    __syncthreads();

    for (int p = tid; p < U_*128; p += 256) {
        int u = p >> 7, kk = p & 127;
        float s = 0.f;
#pragma unroll
        for (int dc = 0; dc < 64; dc += 4) {
            float4 a = *(const float4*)&qs[u][dc];
            float4 c = *(const float4*)&Ks[kk][dc];
            s += a.x*c.x + a.y*c.y + a.z*c.z + a.w*c.w;
        }
        int k = kt0 + kk;
        s *= 0.125f;
        if (mrow[k] == 0) s = -INF_F;
        scp[(size_t)u*L_ + k] = s;
    }
}

// ============================================================
// sparse softmax (in place on g_sc), one block per (b,h)
// ============================================================
__global__ __launch_bounds__(256)
void sp_softmax_kernel()
{
    const int bh = blockIdx.x, tid = threadIdx.x;
    float* scp = g_sc + (size_t)bh*U_*L_;
    const int wid = tid >> 5, lane = tid & 31;
    for (int u = wid; u < U_; u += 8) {
        float mx = -INF_F;
        for (int k = lane; k < L_; k += 32)
            mx = fmaxf(mx, scp[(size_t)u*L_ + k]);
#pragma unroll
        for (int off = 16; off; off >>= 1)
            mx = fmaxf(mx, __shfl_xor_sync(0xffffffffu, mx, off));
        float sm = 0.f;
        for (int k = lane; k < L_; k += 32) {
            float s = scp[(size_t)u*L_ + k];
            sm += (s == -INF_F) ? 0.f : expf(s - mx);
        }
#pragma unroll
        for (int off = 16; off; off >>= 1)
            sm += __shfl_xor_sync(0xffffffffu, sm, off);
        float inv = (sm > 0.f) ? 1.0f / sm : 0.f;
        for (int k = lane; k < L_; k += 32) {
            float s = scp[(size_t)u*L_ + k];
            float pv = (s == -INF_F || mx == -INF_F) ? 0.f : expf(s - mx) * inv;
            scp[(size_t)u*L_ + k] = pv;
        }
    }
}

// ============================================================
// ctx[u,d] = sum_k p[u,k] v[k,d]; scatter into x2
// ============================================================
__global__ __launch_bounds__(256)
void sp_ctx_kernel()
{
    __shared__ float ps[U_][64];
    __shared__ float cb[U_][64];
    __shared__ int   sidx[U_];
    const int bh = blockIdx.x, tid = threadIdx.x;
    const int b = bh >> 3, h = bh & 7;
    const float* vp = g_v + (size_t)bh*L_*D_;
    const float* scp = g_sc + (size_t)bh*U_*L_;
    if (tid < U_) sidx[tid] = g_idx[bh*U_ + tid];

    const int d = tid & 63, part = tid >> 6;
    float acc[U_];
#pragma unroll
    for (int u = 0; u < U_; u++) acc[u] = 0.f;

    for (int kt = 0; kt < L_; kt += 64) {
        __syncthreads();
        for (int i = tid; i < U_*64; i += 256) {
            int u = i >> 6, kk = i & 63;
            ps[u][kk] = scp[(size_t)u*L_ + kt + kk];
        }
        __syncthreads();
        for (int kk = part*16; kk < part*16 + 16; kk++) {
            float v = vp[(size_t)(kt + kk)*D_ + d];
#pragma unroll
            for (int u = 0; u < U_; u++)
                acc[u] += ps[u][kk] * v;
        }
    }
    __syncthreads();
    for (int p2 = 0; p2 < 4; p2++) {
        if (part == p2) {
#pragma unroll
            for (int u = 0; u < U_; u++) {
                if (p2 == 0) cb[u][d] = acc[u];
                else         cb[u][d] += acc[u];
            }
        }
        __syncthreads();
    }
    float* x2 = g_x2 + (size_t)b*L_*F_ + h*D_;
    for (int i = tid; i < U_*64; i += 256) {
        int u = i >> 6, dd = i & 63;
        x2[(size_t)sidx[u]*F_ + dd] = cb[u][dd];
    }
}

// ============================================================
// per-batch mean output row: om[b] = vmconcat @ Wo^T + bo
// ============================================================
__global__ __launch_bounds__(256)
void mean_out_kernel(const float* __restrict__ Wo, const float* __restrict__ bo)
{
    const int b = blockIdx.x, tid = threadIdx.x;
    __shared__ float vms[F_];
    for (int f = tid; f < F_; f += 256)
        vms[f] = g_vm[(b*H_ + (f >> 6))*64 + (f & 63)];
    __syncthreads();
    for (int n = tid; n < F_; n += 256) {
        float s = bo[n];
        const float* w = Wo + (size_t)n*F_;
        for (int f = 0; f < F_; f += 4) {
            float4 wv = *(const float4*)(w + f);
            s += vms[f]*wv.x + vms[f+1]*wv.y + vms[f+2]*wv.z + vms[f+3]*wv.w;
        }
        g_om[b*F_ + n] = s;
    }
}

// broadcast om to all output rows; grid (B_, L_/8)
__global__ __launch_bounds__(256)
void bcast_kernel(float* __restrict__ out)
{
    const int b = blockIdx.x, l0 = blockIdx.y << 3, tid = threadIdx.x;
    __shared__ float om[F_];
    for (int f = tid; f < F_; f += 256) om[f] = g_om[b*F_ + f];
    __syncthreads();
    float2 v = *(const float2*)&om[tid*2];
    float* base = out + ((size_t)b*L_ + l0)*F_;
#pragma unroll
    for (int rr = 0; rr < 8; rr++)
        *(float2*)(base + (size_t)rr*F_ + tid*2) = v;
}

// ============================================================
// output GEMM over only the selected-row union, row-indirected
// grid (4, B_*3)
// ============================================================
__global__ __launch_bounds__(256, 2)
void gemm_rows_kernel(const float* __restrict__ W,
                      const float* __restrict__ bias,
                      float* __restrict__ out)
{
    const int b = blockIdx.y / 3;
    const int t = blockIdx.y % 3;
    const int cnt = g_cnt[b];
    if (t * 128 >= cnt) return;

    __shared__ __align__(16) float As[2][16][132];
    __shared__ __align__(16) float Bs[2][16][132];
    __shared__ int rows_s[128];

    const int tid = threadIdx.x;
    if (tid < 128) {
        int gi = t*128 + tid;
        rows_s[tid] = (gi < cnt) ? g_rows[b*L_ + gi] : g_rows[b*L_];
    }
    __syncthreads();

    const float* X = g_x2 + (size_t)b*L_*F_;
    const int tx = tid & 15, ty = tid >> 4;
    const int n0 = blockIdx.x * 128;
    const int r  = tid >> 2;
    const int kc = (tid & 3) << 2;
    const int mo = r << 1;
    const int l0r = rows_s[r], l1r = rows_s[r + 64];

    u64 acc[4][8];
#pragma unroll
    for (int i = 0; i < 4; i++)
#pragma unroll
        for (int j = 0; j < 8; j++) acc[i][j] = 0ULL;

    float4 ra0, ra1, rb0, rb1;
    ra0 = *(const float4*)(X + (size_t)l0r*F_ + kc);
    ra1 = *(const float4*)(X + (size_t)l1r*F_ + kc);
    rb0 = *(const float4*)(W + (size_t)(n0 + r)*F_ + kc);
    rb1 = *(const float4*)(W + (size_t)(n0 + r + 64)*F_ + kc);

#define GSTORE(bsel) do { \
    As[bsel][kc+0][mo]   = ra0.x; As[bsel][kc+1][mo]   = ra0.y; \
    As[bsel][kc+2][mo]   = ra0.z; As[bsel][kc+3][mo]   = ra0.w; \
    As[bsel][kc+0][mo+1] = ra1.x; As[bsel][kc+1][mo+1] = ra1.y; \
    As[bsel][kc+2][mo+1] = ra1.z; As[bsel][kc+3][mo+1] = ra1.w; \
    Bs[bsel][kc+0][r]    = rb0.x; Bs[bsel][kc+1][r]    = rb0.y; \
    Bs[bsel][kc+2][r]    = rb0.z; Bs[bsel][kc+3][r]    = rb0.w; \
    Bs[bsel][kc+0][r+64] = rb1.x; Bs[bsel][kc+1][r+64] = rb1.y; \
    Bs[bsel][kc+2][r+64] = rb1.z; Bs[bsel][kc+3][r+64] = rb1.w; } while(0)

    GSTORE(0);
    __syncthreads();

    for (int c = 0; c < 32; c++) {
        if (c < 31) {
            int kb = (c + 1) << 4;
            ra0 = *(const float4*)(X + (size_t)l0r*F_ + kb + kc);
            ra1 = *(const float4*)(X + (size_t)l1r*F_ + kb + kc);
            rb0 = *(const float4*)(W + (size_t)(n0 + r)*F_ + kb + kc);
            rb1 = *(const float4*)(W + (size_t)(n0 + r + 64)*F_ + kb + kc);
        }
        const int bsel = c & 1;
#pragma unroll
        for (int kk = 0; kk < 16; kk++) {
            ulonglong2 a01 = *(const ulonglong2*)&As[bsel][kk][ty << 3];
            ulonglong2 a23 = *(const ulonglong2*)&As[bsel][kk][(ty << 3) + 4];
            float4 b0 = *(const float4*)&Bs[bsel][kk][tx << 3];
            float4 b1 = *(const float4*)&Bs[bsel][kk][(tx << 3) + 4];
            u64 av[4] = {a01.x, a01.y, a23.x, a23.y};
            u64 bv[8] = {dup2(b0.x), dup2(b0.y), dup2(b0.z), dup2(b0.w),
                         dup2(b1.x), dup2(b1.y), dup2(b1.z), dup2(b1.w)};
#pragma unroll
            for (int i = 0; i < 4; i++)
#pragma unroll
                for (int j = 0; j < 8; j++)
                    fma2(acc[i][j], av[i], bv[j]);
        }
        if (c < 31) GSTORE((c + 1) & 1);
        __syncthreads();
    }
#undef GSTORE

    const int nb = n0 + (tx << 3);
    float bb[8];
#pragma unroll
    for (int j = 0; j < 8; j++) bb[j] = bias[nb + j];

#pragma unroll
    for (int i = 0; i < 4; i++) {
        float lo[8], hi[8];
#pragma unroll
        for (int j = 0; j < 8; j++) {
            float2 tt = unpk(acc[i][j]);
            lo[j] = tt.x + bb[j];
            hi[j] = tt.y + bb[j];
        }
        {
            int l = rows_s[(ty << 2) + i];
            float* p = out + ((size_t)b*L_ + l)*F_ + nb;
            *(float4*)p     = make_float4(lo[0], lo[1], lo[2], lo[3]);
            *(float4*)(p+4) = make_float4(lo[4], lo[5], lo[6], lo[7]);
        }
        {
            int l = rows_s[(ty << 2) + i + 64];
            float* p = out + ((size_t)b*L_ + l)*F_ + nb;
            *(float4*)p     = make_float4(hi[0], hi[1], hi[2], hi[3]);
            *(float4*)(p+4) = make_float4(hi[4], hi[5], hi[6], hi[7]);
        }
    }
}

// ============================================================
extern "C" void kernel_launch(void* const* d_in, const int* in_sizes, int n_in,
                              void* d_out, int out_size)
{
    const float* query = (const float*)d_in[0];
    const float* key   = (const float*)d_in[1];
    const float* value = (const float*)d_in[2];
    const int*   mask  = (const int*)  d_in[3];
    const float* Wq = (const float*)d_in[4];
    const float* bq = (const float*)d_in[5];
    const float* Wk = (const float*)d_in[6];
    const float* bk = (const float*)d_in[7];
    const float* Wv = (const float*)d_in[8];
    const float* bv = (const float*)d_in[9];
    const float* Wo = (const float*)d_in[10];
    const float* bo = (const float*)d_in[11];
    float* out = (float*)d_out;

    float *qd, *kd, *vd;
    cudaGetSymbolAddress((void**)&qd, g_q);
    cudaGetSymbolAddress((void**)&kd, g_k);
    cudaGetSymbolAddress((void**)&vd, g_v);

    zero_kernel<<<64, 256>>>();

    dim3 gg(F_/128, ML_/128);   // (4, 128)
    gemm3_kernel<1><<<gg, 256>>>(query, Wq, bq, qd);
    gemm3_kernel<1><<<gg, 256>>>(key,   Wk, bk, kd);
    gemm3_kernel<1><<<gg, 256>>>(value, Wv, bv, vd);

    dim3 gm(L_/128, BH_);       // (8, 128)
    qk_m3_kernel<<<gm, 256>>>();

    topk_warp_kernel<<<BH_/8, 256>>>();
    vmean_kernel<<<BH_, 256>>>();
    compact_kernel<<<(BH_*U_ + 255)/256, 256>>>();
    x2init_kernel<<<dim3(B_, 3), 256>>>();

    sp_scores_kernel<<<dim3(BH_, 8), 256>>>(mask);
    sp_softmax_kernel<<<BH_, 256>>>();
    sp_ctx_kernel<<<BH_, 256>>>();

    mean_out_kernel<<<B_, 256>>>(Wo, bo);
    bcast_kernel<<<dim3(B_, L_/8), 256>>>(out);
    gemm_rows_kernel<<<dim3(F_/128, B_*3), 256>>>(Wo, bo, out);
}

// round 4
// speedup vs baseline: 1.2960x; 1.0008x over previous
#include <cuda_runtime.h>
#include <cstdint>

typedef unsigned long long u64;

#define B_  16
#define L_  1024
#define F_  512
#define H_  8
#define D_  64
#define U_  35
#define BH_ (B_*H_)     // 128
#define ML_ (B_*L_)     // 16384

#define INF_F __int_as_float(0x7f800000)

// -------- device scratch (no allocations allowed) --------
__device__ float g_q[(size_t)BH_*L_*D_];     // (B,H,L,D)
__device__ float g_k[(size_t)BH_*L_*D_];
__device__ float g_v[(size_t)BH_*L_*D_];
__device__ float g_M[(size_t)BH_*L_];
__device__ int   g_idx[BH_*U_];
__device__ float g_x2[(size_t)ML_*F_];       // context rows (only selected rows valid)
__device__ float g_sc[(size_t)BH_*U_*L_];    // sparse scores / probs
__device__ float g_vm[BH_*D_];               // per-(b,h) V mean
__device__ float g_om[B_*F_];                // per-b mean-output row
__device__ int   g_flag[B_*L_];
__device__ int   g_cnt[B_];
__device__ int   g_rows[B_*L_];

// -------- f32x2 helpers --------
__device__ __forceinline__ void fma2(u64 &acc, u64 a, u64 b) {
    asm("fma.rn.f32x2 %0, %1, %2, %0;" : "+l"(acc) : "l"(a), "l"(b));
}
__device__ __forceinline__ u64 dup2(float v) {
    u64 r; asm("mov.b64 %0, {%1, %1};" : "=l"(r) : "f"(v)); return r;
}
__device__ __forceinline__ float2 unpk(u64 v) {
    float2 r; asm("mov.b64 {%0, %1}, %2;" : "=f"(r.x), "=f"(r.y) : "l"(v)); return r;
}

// ============================================================
// GEMM: C[M,N] = X[M,K] @ W[N,K]^T + bias ; M=16384, N=K=512
// 128x128 tile, 256 threads, 8x8 micro (f32x2 row-pairs),
// double-buffered smem, one sync per 16-k chunk, 2 blocks/SM.
// ============================================================
template<int ATTN>
__global__ __launch_bounds__(256, 2)
void gemm3_kernel(const float* __restrict__ X,
                  const float* __restrict__ W,
                  const float* __restrict__ bias,
                  float* __restrict__ out)
{
    __shared__ __align__(16) float As[2][16][132];
    __shared__ __align__(16) float Bs[2][16][132];
    const int tid = threadIdx.x;
    const int tx = tid & 15, ty = tid >> 4;
    const int m0 = blockIdx.y * 128, n0 = blockIdx.x * 128;
    const int r  = tid >> 2;            // 0..63
    const int kc = (tid & 3) << 2;      // 0,4,8,12
    const int mo = r << 1;

    u64 acc[4][8];
#pragma unroll
    for (int i = 0; i < 4; i++)
#pragma unroll
        for (int j = 0; j < 8; j++) acc[i][j] = 0ULL;

    float4 ra0, ra1, rb0, rb1;
    ra0 = *(const float4*)(X + (size_t)(m0 + r)*F_ + kc);
    ra1 = *(const float4*)(X + (size_t)(m0 + r + 64)*F_ + kc);
    rb0 = *(const float4*)(W + (size_t)(n0 + r)*F_ + kc);
    rb1 = *(const float4*)(W + (size_t)(n0 + r + 64)*F_ + kc);

#define GSTORE(bsel) do { \
    As[bsel][kc+0][mo]   = ra0.x; As[bsel][kc+1][mo]   = ra0.y; \
    As[bsel][kc+2][mo]   = ra0.z; As[bsel][kc+3][mo]   = ra0.w; \
    As[bsel][kc+0][mo+1] = ra1.x; As[bsel][kc+1][mo+1] = ra1.y; \
    As[bsel][kc+2][mo+1] = ra1.z; As[bsel][kc+3][mo+1] = ra1.w; \
    Bs[bsel][kc+0][r]    = rb0.x; Bs[bsel][kc+1][r]    = rb0.y; \
    Bs[bsel][kc+2][r]    = rb0.z; Bs[bsel][kc+3][r]    = rb0.w; \
    Bs[bsel][kc+0][r+64] = rb1.x; Bs[bsel][kc+1][r+64] = rb1.y; \
    Bs[bsel][kc+2][r+64] = rb1.z; Bs[bsel][kc+3][r+64] = rb1.w; } while(0)

    GSTORE(0);
    __syncthreads();

    for (int c = 0; c < 32; c++) {
        if (c < 31) {
            int kb = (c + 1) << 4;
            ra0 = *(const float4*)(X + (size_t)(m0 + r)*F_ + kb + kc);
            ra1 = *(const float4*)(X + (size_t)(m0 + r + 64)*F_ + kb + kc);
            rb0 = *(const float4*)(W + (size_t)(n0 + r)*F_ + kb + kc);
            rb1 = *(const float4*)(W + (size_t)(n0 + r + 64)*F_ + kb + kc);
        }
        const int bsel = c & 1;
#pragma unroll
        for (int kk = 0; kk < 16; kk++) {
            ulonglong2 a01 = *(const ulonglong2*)&As[bsel][kk][ty << 3];
            ulonglong2 a23 = *(const ulonglong2*)&As[bsel][kk][(ty << 3) + 4];
            float4 b0 = *(const float4*)&Bs[bsel][kk][tx << 3];
            float4 b1 = *(const float4*)&Bs[bsel][kk][(tx << 3) + 4];
            u64 av[4] = {a01.x, a01.y, a23.x, a23.y};
            u64 bv[8] = {dup2(b0.x), dup2(b0.y), dup2(b0.z), dup2(b0.w),
                         dup2(b1.x), dup2(b1.y), dup2(b1.z), dup2(b1.w)};
#pragma unroll
            for (int i = 0; i < 4; i++)
#pragma unroll
                for (int j = 0; j < 8; j++)
                    fma2(acc[i][j], av[i], bv[j]);
        }
        if (c < 31) GSTORE((c + 1) & 1);
        __syncthreads();
    }
#undef GSTORE

    const int nb = n0 + (tx << 3);
    float bb[8];
#pragma unroll
    for (int j = 0; j < 8; j++) bb[j] = bias[nb + j];

#pragma unroll
    for (int i = 0; i < 4; i++) {
        float lo[8], hi[8];
#pragma unroll
        for (int j = 0; j < 8; j++) {
            float2 t = unpk(acc[i][j]);
            lo[j] = t.x + bb[j];
            hi[j] = t.y + bb[j];
        }
        {
            int m = m0 + (ty << 2) + i;
            float* p;
            if (ATTN) {
                int b = m >> 10, l = m & (L_-1);
                int h = nb >> 6, d = nb & (D_-1);
                p = out + ((size_t)(b*H_ + h)*L_ + l)*D_ + d;
            } else {
                p = out + (size_t)m*F_ + nb;
            }
            *(float4*)p     = make_float4(lo[0], lo[1], lo[2], lo[3]);
            *(float4*)(p+4) = make_float4(lo[4], lo[5], lo[6], lo[7]);
        }
        {
            int m = m0 + (ty << 2) + i + 64;
            float* p;
            if (ATTN) {
                int b = m >> 10, l = m & (L_-1);
                int h = nb >> 6, d = nb & (D_-1);
                p = out + ((size_t)(b*H_ + h)*L_ + l)*D_ + d;
            } else {
                p = out + (size_t)m*F_ + nb;
            }
            *(float4*)p     = make_float4(hi[0], hi[1], hi[2], hi[3]);
            *(float4*)(p+4) = make_float4(hi[4], hi[5], hi[6], hi[7]);
        }
    }
}

// ============================================================
// M[b,h,q] = max_k(q.k) - mean_k(q.k); Q tile resident, K
// double-buffered in 8-d chunks, one sync per chunk, 2 blk/SM.
// grid: (L/128, BH), block 256
// ============================================================
__global__ __launch_bounds__(256, 2)
void qk_m3_kernel()
{
    __shared__ float Qs[64][130];        // [d][q-pair-interleaved]
    __shared__ float Ks[2][8][130];      // [d-chunk][k]
    const int tid = threadIdx.x;
    const int tx = tid & 15, ty = tid >> 4;
    const int bh = blockIdx.y;
    const int q0 = blockIdx.x * 128;
    const float* qp = g_q + (size_t)bh*L_*D_;
    const float* kp = g_k + (size_t)bh*L_*D_;

#pragma unroll
    for (int i = 0; i < 8; i++) {
        int idx = tid + i*256;
        int q = idx >> 4, dc = (idx & 15) << 2;
        float4 v = *(const float4*)(qp + (size_t)(q0 + q)*D_ + dc);
        int qo = ((q & 63) << 1) | (q >> 6);
        Qs[dc+0][qo] = v.x; Qs[dc+1][qo] = v.y;
        Qs[dc+2][qo] = v.z; Qs[dc+3][qo] = v.w;
    }

    const int kr  = tid >> 1;            // 0..127
    const int dc2 = (tid & 1) << 2;      // 0 or 4

    float rmax[8], rsum[8];
#pragma unroll
    for (int r2 = 0; r2 < 8; r2++) { rmax[r2] = -INF_F; rsum[r2] = 0.f; }
    u64 acc[4][8];

    float4 rk = *(const float4*)(kp + (size_t)kr*D_ + dc2);
#define KST(bsel) do { \
    Ks[bsel][dc2+0][kr] = rk.x; Ks[bsel][dc2+1][kr] = rk.y; \
    Ks[bsel][dc2+2][kr] = rk.z; Ks[bsel][dc2+3][kr] = rk.w; } while(0)
    KST(0);
    __syncthreads();

    // 64 chunks = 8 k-tiles(128) x 8 d-chunks(8)
    for (int c = 0; c < 64; c++) {
        if ((c & 7) == 0) {
#pragma unroll
            for (int i = 0; i < 4; i++)
#pragma unroll
                for (int j = 0; j < 8; j++) acc[i][j] = 0ULL;
        }
        if (c < 63) {
            int ktn = ((c+1) >> 3) << 7;
            int d0n = ((c+1) & 7) << 3;
            rk = *(const float4*)(kp + (size_t)(ktn + kr)*D_ + d0n + dc2);
        }
        const int bsel = c & 1;
        const int d0 = (c & 7) << 3;
#pragma unroll
        for (int dd = 0; dd < 8; dd++) {
            const float* qrow = &Qs[d0+dd][ty << 3];
            u64 av[4];
            av[0] = *(const u64*)(qrow);
            av[1] = *(const u64*)(qrow + 2);
            av[2] = *(const u64*)(qrow + 4);
            av[3] = *(const u64*)(qrow + 6);
            const float* krow = &Ks[bsel][dd][tx << 3];
            u64 bv[8];
#pragma unroll
            for (int j2 = 0; j2 < 4; j2++) {
                float2 b2 = *(const float2*)(krow + (j2 << 1));
                bv[j2*2]   = dup2(b2.x);
                bv[j2*2+1] = dup2(b2.y);
            }
#pragma unroll
            for (int i = 0; i < 4; i++)
#pragma unroll
                for (int j = 0; j < 8; j++)
                    fma2(acc[i][j], av[i], bv[j]);
        }
        if ((c & 7) == 7) {
#pragma unroll
            for (int i = 0; i < 4; i++) {
                float mLo = -INF_F, mHi = -INF_F, sLo = 0.f, sHi = 0.f;
#pragma unroll
                for (int j = 0; j < 8; j++) {
                    float2 t2 = unpk(acc[i][j]);
                    mLo = fmaxf(mLo, t2.x); sLo += t2.x;
                    mHi = fmaxf(mHi, t2.y); sHi += t2.y;
                }
                rmax[i]   = fmaxf(rmax[i],   mLo); rsum[i]   += sLo;
                rmax[i+4] = fmaxf(rmax[i+4], mHi); rsum[i+4] += sHi;
            }
        }
        if (c < 63) KST((c+1) & 1);
        __syncthreads();
    }
#undef KST

#pragma unroll
    for (int r2 = 0; r2 < 8; r2++) {
        float m = rmax[r2], s = rsum[r2];
#pragma unroll
        for (int off = 8; off; off >>= 1) {
            m = fmaxf(m, __shfl_xor_sync(0xffffffffu, m, off));
            s += __shfl_xor_sync(0xffffffffu, s, off);
        }
        rmax[r2] = m; rsum[r2] = s;
    }
    if (tx == 0) {
#pragma unroll
        for (int r2 = 0; r2 < 8; r2++) {
            int row = q0 + (ty << 2) + (r2 & 3) + ((r2 >> 2) << 6);
            g_M[(size_t)bh*L_ + row] = rmax[r2] - rsum[r2] * (1.0f/L_);
        }
    }
}

// ============================================================
// warp-private top-35 (one warp per (b,h), values in registers)
// ============================================================
__global__ __launch_bounds__(256)
void topk_warp_kernel()
{
    const int warp = threadIdx.x >> 5, lane = threadIdx.x & 31;
    const int bh = blockIdx.x * 8 + warp;
    const float* Mp = g_M + (size_t)bh*L_;
    float v[32];
#pragma unroll
    for (int j = 0; j < 32; j++) v[j] = Mp[j*32 + lane];

    for (int it = 0; it < U_; it++) {
        float bv = v[0]; int bj = 0;
#pragma unroll
        for (int j = 1; j < 32; j++)
            if (v[j] > bv) { bv = v[j]; bj = j; }
        int bk = bj*32 + lane;
#pragma unroll
        for (int off = 16; off; off >>= 1) {
            float ov = __shfl_xor_sync(0xffffffffu, bv, off);
            int   ok = __shfl_xor_sync(0xffffffffu, bk, off);
            if (ov > bv || (ov == bv && ok < bk)) { bv = ov; bk = ok; }
        }
        if (lane == 0) g_idx[bh*U_ + it] = bk;
        int cj = bk >> 5;
        bool mine = ((bk & 31) == lane);
#pragma unroll
        for (int j = 0; j < 32; j++)
            if (mine && j == cj) v[j] = -INF_F;
    }
}

// ============================================================
// vm[b,h,d] = mean over l of v
// ============================================================
__global__ __launch_bounds__(256)
void vmean_kernel()
{
    const int bh = blockIdx.x, tid = threadIdx.x;
    const int d = tid & 63, part = tid >> 6;
    const float* vp = g_v + (size_t)bh*L_*D_;
    float acc = 0.f;
    for (int l = part*256; l < part*256 + 256; l++)
        acc += vp[(size_t)l*D_ + d];
    __shared__ float red[4][64];
    red[part][d] = acc;
    __syncthreads();
    if (tid < 64)
        g_vm[bh*64 + tid] =
            (red[0][tid] + red[1][tid] + red[2][tid] + red[3][tid]) * (1.0f/L_);
}

// ============================================================
// flags/counters reset + selected-row compaction per batch
// ============================================================
__global__ void zero_kernel()
{
    int t = blockIdx.x*256 + threadIdx.x;
    if (t < B_*L_) g_flag[t] = 0;
    if (t < B_)    g_cnt[t]  = 0;
}

__global__ void compact_kernel()
{
    int t = blockIdx.x*256 + threadIdx.x;
    if (t >= BH_*U_) return;
    int bh = t / U_;
    int b  = bh >> 3;
    int row = g_idx[t];
    if (atomicExch(&g_flag[b*L_ + row], 1) == 0) {
        int p = atomicAdd(&g_cnt[b], 1);
        g_rows[b*L_ + p] = row;
    }
}

// ============================================================
// init x2 rows in the selected union with vm-concat
// grid (B_, 3)
// ============================================================
__global__ __launch_bounds__(256)
void x2init_kernel()
{
    const int b = blockIdx.x, t = blockIdx.y, tid = threadIdx.x;
    __shared__ float vms[F_];
    for (int f = tid; f < F_; f += 256)
        vms[f] = g_vm[(b*H_ + (f >> 6))*64 + (f & 63)];
    __syncthreads();
    const int cnt = g_cnt[b];
    int hiR = t*128 + 128; if (hiR > cnt) hiR = cnt;
    for (int ri = t*128; ri < hiR; ri++) {
        int l = g_rows[b*L_ + ri];
        float* p = g_x2 + ((size_t)b*L_ + l)*F_;
        p[tid]       = vms[tid];
        p[tid + 256] = vms[tid + 256];
    }
}

// ============================================================
// sparse scores: grid (BH_, 8); block does 35u x 128k
// ============================================================
__global__ __launch_bounds__(256)
void sp_scores_kernel(const int* __restrict__ mask)
{
    __shared__ float qs[U_][64];
    __shared__ float Ks[128][68];
    __shared__ int   sidx[U_];
    const int bh = blockIdx.x, tid = threadIdx.x;
    const int b = bh >> 3;
    const int kt0 = blockIdx.y << 7;
    const float* qp = g_q + (size_t)bh*L_*D_;
    const float* kp = g_k + (size_t)bh*L_*D_;
    float* scp = g_sc + (size_t)bh*U_*L_;
    const int* mrow = mask + b*L_;

    if (tid < U_) sidx[tid] = g_idx[bh*U_ + tid];
    __syncthreads();
    for (int i = tid; i < U_*16; i += 256) {
        int u = i >> 4, dc = (i & 15) << 2;
        *(float4*)&qs[u][dc] = *(const float4*)(qp + (size_t)sidx[u]*D_ + dc);
    }
    for (int i = tid; i < 128*16; i += 256) {
        int k = i >> 4, dc = (i & 15) << 2;
        *(float4*)&Ks[k][dc] = *(const float4*)(kp + (size_t)(kt0 + k)*D_ + dc);
    }
    __syncthreads();

    for (int p = tid; p < U_*128; p += 256) {
        int u = p >> 7, kk = p & 127;
        float s = 0.f;
#pragma unroll
        for (int dc = 0; dc < 64; dc += 4) {
            float4 a = *(const float4*)&qs[u][dc];
            float4 c = *(const float4*)&Ks[kk][dc];
            s += a.x*c.x + a.y*c.y + a.z*c.z + a.w*c.w;
        }
        int k = kt0 + kk;
        s *= 0.125f;
        if (mrow[k] == 0) s = -INF_F;
        scp[(size_t)u*L_ + k] = s;
    }
}

// ============================================================
// sparse softmax (in place on g_sc), one block per (b,h)
// ============================================================
__global__ __launch_bounds__(256)
void sp_softmax_kernel()
{
    const int bh = blockIdx.x, tid = threadIdx.x;
    float* scp = g_sc + (size_t)bh*U_*L_;
    const int wid = tid >> 5, lane = tid & 31;
    for (int u = wid; u < U_; u += 8) {
        float mx = -INF_F;
        for (int k = lane; k < L_; k += 32)
            mx = fmaxf(mx, scp[(size_t)u*L_ + k]);
#pragma unroll
        for (int off = 16; off; off >>= 1)
            mx = fmaxf(mx, __shfl_xor_sync(0xffffffffu, mx, off));
        float sm = 0.f;
        for (int k = lane; k < L_; k += 32) {
            float s = scp[(size_t)u*L_ + k];
            sm += (s == -INF_F) ? 0.f : expf(s - mx);
        }
#pragma unroll
        for (int off = 16; off; off >>= 1)
            sm += __shfl_xor_sync(0xffffffffu, sm, off);
        float inv = (sm > 0.f) ? 1.0f / sm : 0.f;
        for (int k = lane; k < L_; k += 32) {
            float s = scp[(size_t)u*L_ + k];
            float pv = (s == -INF_F || mx == -INF_F) ? 0.f : expf(s - mx) * inv;
            scp[(size_t)u*L_ + k] = pv;
        }
    }
}

// ============================================================
// ctx[u,d] = sum_k p[u,k] v[k,d]; scatter into x2
// ============================================================
__global__ __launch_bounds__(256)
void sp_ctx_kernel()
{
    __shared__ float ps[U_][64];
    __shared__ float cb[U_][64];
    __shared__ int   sidx[U_];
    const int bh = blockIdx.x, tid = threadIdx.x;
    const int b = bh >> 3, h = bh & 7;
    const float* vp = g_v + (size_t)bh*L_*D_;
    const float* scp = g_sc + (size_t)bh*U_*L_;
    if (tid < U_) sidx[tid] = g_idx[bh*U_ + tid];

    const int d = tid & 63, part = tid >> 6;
    float acc[U_];
#pragma unroll
    for (int u = 0; u < U_; u++) acc[u] = 0.f;

    for (int kt = 0; kt < L_; kt += 64) {
        __syncthreads();
        for (int i = tid; i < U_*64; i += 256) {
            int u = i >> 6, kk = i & 63;
            ps[u][kk] = scp[(size_t)u*L_ + kt + kk];
        }
        __syncthreads();
        for (int kk = part*16; kk < part*16 + 16; kk++) {
            float v = vp[(size_t)(kt + kk)*D_ + d];
#pragma unroll
            for (int u = 0; u < U_; u++)
                acc[u] += ps[u][kk] * v;
        }
    }
    __syncthreads();
    for (int p2 = 0; p2 < 4; p2++) {
        if (part == p2) {
#pragma unroll
            for (int u = 0; u < U_; u++) {
                if (p2 == 0) cb[u][d] = acc[u];
                else         cb[u][d] += acc[u];
            }
        }
        __syncthreads();
    }
    float* x2 = g_x2 + (size_t)b*L_*F_ + h*D_;
    for (int i = tid; i < U_*64; i += 256) {
        int u = i >> 6, dd = i & 63;
        x2[(size_t)sidx[u]*F_ + dd] = cb[u][dd];
    }
}

// ============================================================
// per-batch mean output row: om[b] = vmconcat @ Wo^T + bo
// ============================================================
__global__ __launch_bounds__(256)
void mean_out_kernel(const float* __restrict__ Wo, const float* __restrict__ bo)
{
    const int b = blockIdx.x, tid = threadIdx.x;
    __shared__ float vms[F_];
    for (int f = tid; f < F_; f += 256)
        vms[f] = g_vm[(b*H_ + (f >> 6))*64 + (f & 63)];
    __syncthreads();
    for (int n = tid; n < F_; n += 256) {
        float s = bo[n];
        const float* w = Wo + (size_t)n*F_;
        for (int f = 0; f < F_; f += 4) {
            float4 wv = *(const float4*)(w + f);
            s += vms[f]*wv.x + vms[f+1]*wv.y + vms[f+2]*wv.z + vms[f+3]*wv.w;
        }
        g_om[b*F_ + n] = s;
    }
}

// broadcast om to all output rows; grid (B_, L_/8)
__global__ __launch_bounds__(256)
void bcast_kernel(float* __restrict__ out)
{
    const int b = blockIdx.x, l0 = blockIdx.y << 3, tid = threadIdx.x;
    __shared__ float om[F_];
    for (int f = tid; f < F_; f += 256) om[f] = g_om[b*F_ + f];
    __syncthreads();
    float2 v = *(const float2*)&om[tid*2];
    float* base = out + ((size_t)b*L_ + l0)*F_;
#pragma unroll
    for (int rr = 0; rr < 8; rr++)
        *(float2*)(base + (size_t)rr*F_ + tid*2) = v;
}

// ============================================================
// output GEMM over only the selected-row union, row-indirected
// grid (4, B_*3)
// ============================================================
__global__ __launch_bounds__(256, 2)
void gemm_rows_kernel(const float* __restrict__ W,
                      const float* __restrict__ bias,
                      float* __restrict__ out)
{
    const int b = blockIdx.y / 3;
    const int t = blockIdx.y % 3;
    const int cnt = g_cnt[b];
    if (t * 128 >= cnt) return;

    __shared__ __align__(16) float As[2][16][132];
    __shared__ __align__(16) float Bs[2][16][132];
    __shared__ int rows_s[128];

    const int tid = threadIdx.x;
    if (tid < 128) {
        int gi = t*128 + tid;
        rows_s[tid] = (gi < cnt) ? g_rows[b*L_ + gi] : g_rows[b*L_];
    }
    __syncthreads();

    const float* X = g_x2 + (size_t)b*L_*F_;
    const int tx = tid & 15, ty = tid >> 4;
    const int n0 = blockIdx.x * 128;
    const int r  = tid >> 2;
    const int kc = (tid & 3) << 2;
    const int mo = r << 1;
    const int l0r = rows_s[r], l1r = rows_s[r + 64];

    u64 acc[4][8];
#pragma unroll
    for (int i = 0; i < 4; i++)
#pragma unroll
        for (int j = 0; j < 8; j++) acc[i][j] = 0ULL;

    float4 ra0, ra1, rb0, rb1;
    ra0 = *(const float4*)(X + (size_t)l0r*F_ + kc);
    ra1 = *(const float4*)(X + (size_t)l1r*F_ + kc);
    rb0 = *(const float4*)(W + (size_t)(n0 + r)*F_ + kc);
    rb1 = *(const float4*)(W + (size_t)(n0 + r + 64)*F_ + kc);

#define GSTORE(bsel) do { \
    As[bsel][kc+0][mo]   = ra0.x; As[bsel][kc+1][mo]   = ra0.y; \
    As[bsel][kc+2][mo]   = ra0.z; As[bsel][kc+3][mo]   = ra0.w; \
    As[bsel][kc+0][mo+1] = ra1.x; As[bsel][kc+1][mo+1] = ra1.y; \
    As[bsel][kc+2][mo+1] = ra1.z; As[bsel][kc+3][mo+1] = ra1.w; \
    Bs[bsel][kc+0][r]    = rb0.x; Bs[bsel][kc+1][r]    = rb0.y; \
    Bs[bsel][kc+2][r]    = rb0.z; Bs[bsel][kc+3][r]    = rb0.w; \
    Bs[bsel][kc+0][r+64] = rb1.x; Bs[bsel][kc+1][r+64] = rb1.y; \
    Bs[bsel][kc+2][r+64] = rb1.z; Bs[bsel][kc+3][r+64] = rb1.w; } while(0)

    GSTORE(0);
    __syncthreads();

    for (int c = 0; c < 32; c++) {
        if (c < 31) {
            int kb = (c + 1) << 4;
            ra0 = *(const float4*)(X + (size_t)l0r*F_ + kb + kc);
            ra1 = *(const float4*)(X + (size_t)l1r*F_ + kb + kc);
            rb0 = *(const float4*)(W + (size_t)(n0 + r)*F_ + kb + kc);
            rb1 = *(const float4*)(W + (size_t)(n0 + r + 64)*F_ + kb + kc);
        }
        const int bsel = c & 1;
#pragma unroll
        for (int kk = 0; kk < 16; kk++) {
            ulonglong2 a01 = *(const ulonglong2*)&As[bsel][kk][ty << 3];
            ulonglong2 a23 = *(const ulonglong2*)&As[bsel][kk][(ty << 3) + 4];
            float4 b0 = *(const float4*)&Bs[bsel][kk][tx << 3];
            float4 b1 = *(const float4*)&Bs[bsel][kk][(tx << 3) + 4];
            u64 av[4] = {a01.x, a01.y, a23.x, a23.y};
            u64 bv[8] = {dup2(b0.x), dup2(b0.y), dup2(b0.z), dup2(b0.w),
                         dup2(b1.x), dup2(b1.y), dup2(b1.z), dup2(b1.w)};
#pragma unroll
            for (int i = 0; i < 4; i++)
#pragma unroll
                for (int j = 0; j < 8; j++)
                    fma2(acc[i][j], av[i], bv[j]);
        }
        if (c < 31) GSTORE((c + 1) & 1);
        __syncthreads();
    }
#undef GSTORE

    const int nb = n0 + (tx << 3);
    float bb[8];
#pragma unroll
    for (int j = 0; j < 8; j++) bb[j] = bias[nb + j];

#pragma unroll
    for (int i = 0; i < 4; i++) {
        float lo[8], hi[8];
#pragma unroll
        for (int j = 0; j < 8; j++) {
            float2 tt = unpk(acc[i][j]);
            lo[j] = tt.x + bb[j];
            hi[j] = tt.y + bb[j];
        }
        {
            int l = rows_s[(ty << 2) + i];
            float* p = out + ((size_t)b*L_ + l)*F_ + nb;
            *(float4*)p     = make_float4(lo[0], lo[1], lo[2], lo[3]);
            *(float4*)(p+4) = make_float4(lo[4], lo[5], lo[6], lo[7]);
        }
        {
            int l = rows_s[(ty << 2) + i + 64];
            float* p = out + ((size_t)b*L_ + l)*F_ + nb;
            *(float4*)p     = make_float4(hi[0], hi[1], hi[2], hi[3]);
            *(float4*)(p+4) = make_float4(hi[4], hi[5], hi[6], hi[7]);
        }
    }
}

// ============================================================
extern "C" void kernel_launch(void* const* d_in, const int* in_sizes, int n_in,
                              void* d_out, int out_size)
{
    const float* query = (const float*)d_in[0];
    const float* key   = (const float*)d_in[1];
    const float* value = (const float*)d_in[2];
    const int*   mask  = (const int*)  d_in[3];
    const float* Wq = (const float*)d_in[4];
    const float* bq = (const float*)d_in[5];
    const float* Wk = (const float*)d_in[6];
    const float* bk = (const float*)d_in[7];
    const float* Wv = (const float*)d_in[8];
    const float* bv = (const float*)d_in[9];
    const float* Wo = (const float*)d_in[10];
    const float* bo = (const float*)d_in[11];
    float* out = (float*)d_out;

    float *qd, *kd, *vd;
    cudaGetSymbolAddress((void**)&qd, g_q);
    cudaGetSymbolAddress((void**)&kd, g_k);
    cudaGetSymbolAddress((void**)&vd, g_v);

    zero_kernel<<<64, 256>>>();

    dim3 gg(F_/128, ML_/128);   // (4, 128)
    gemm3_kernel<1><<<gg, 256>>>(query, Wq, bq, qd);
    gemm3_kernel<1><<<gg, 256>>>(key,   Wk, bk, kd);
    gemm3_kernel<1><<<gg, 256>>>(value, Wv, bv, vd);

    dim3 gm(L_/128, BH_);       // (8, 128)
    qk_m3_kernel<<<gm, 256>>>();

    topk_warp_kernel<<<BH_/8, 256>>>();
    vmean_kernel<<<BH_, 256>>>();
    compact_kernel<<<(BH_*U_ + 255)/256, 256>>>();
    x2init_kernel<<<dim3(B_, 3), 256>>>();

    sp_scores_kernel<<<dim3(BH_, 8), 256>>>(mask);
    sp_softmax_kernel<<<BH_, 256>>>();
    sp_ctx_kernel<<<BH_, 256>>>();

    mean_out_kernel<<<B_, 256>>>(Wo, bo);
    bcast_kernel<<<dim3(B_, L_/8), 256>>>(out);
    gemm_rows_kernel<<<dim3(F_/128, B_*3), 256>>>(Wo, bo, out);
}

// round 7
// speedup vs baseline: 1.7078x; 1.3177x over previous
#include <cuda_runtime.h>
#include <cuda_bf16.h>
#include <cstdint>

typedef unsigned long long u64;

#define B_  16
#define L_  1024
#define F_  512
#define H_  8
#define D_  64
#define U_  35
#define BH_ (B_*H_)
#define ML_ (B_*L_)

#define INF_F __int_as_float(0x7f800000)

// -------- device scratch --------
__device__ float g_q[(size_t)BH_*L_*D_];
__device__ float g_k[(size_t)BH_*L_*D_];
__device__ float g_v[(size_t)BH_*L_*D_];
__device__ float g_M[(size_t)BH_*L_];
__device__ int   g_idx[BH_*U_];
__device__ float g_x2[(size_t)ML_*F_];
__device__ float g_sc[(size_t)BH_*U_*L_];
__device__ float g_vm[BH_*D_];
__device__ float g_om[B_*F_];
__device__ int   g_flag[B_*L_];
__device__ int   g_cnt[B_];
__device__ int   g_rows[B_*L_];
__device__ __nv_bfloat16 g_xcat[3ULL*ML_*1024];  // [hi(512)|lo(512)] per row
__device__ __nv_bfloat16 g_wcat[3ULL*F_*1024];

// -------- f32x2 helpers --------
__device__ __forceinline__ void fma2(u64 &acc, u64 a, u64 b) {
    asm("fma.rn.f32x2 %0, %1, %2, %0;" : "+l"(acc) : "l"(a), "l"(b));
}
__device__ __forceinline__ u64 dup2(float v) {
    u64 r; asm("mov.b64 %0, {%1, %1};" : "=l"(r) : "f"(v)); return r;
}
__device__ __forceinline__ float2 unpk(u64 v) {
    float2 r; asm("mov.b64 {%0, %1}, %2;" : "=f"(r.x), "=f"(r.y) : "l"(v)); return r;
}

// -------- mma.sync helpers (baseline PTX, sm_80+) --------
__device__ __forceinline__ uint32_t smem_u32(const void* p) {
    uint32_t a;
    asm("{ .reg .u64 t; cvta.to.shared.u64 t, %1; cvt.u32.u64 %0, t; }" : "=r"(a) : "l"(p));
    return a;
}
#define LDSM4(r, addr) \
    asm volatile("ldmatrix.sync.aligned.m8n8.x4.shared.b16 {%0,%1,%2,%3}, [%4];" \
        : "=r"((r)[0]), "=r"((r)[1]), "=r"((r)[2]), "=r"((r)[3]) : "r"(addr))
#define MMA16816(c, a, b0v, b1v) \
    asm volatile("mma.sync.aligned.m16n8k16.row.col.f32.bf16.bf16.f32 " \
        "{%0,%1,%2,%3}, {%4,%5,%6,%7}, {%8,%9}, {%0,%1,%2,%3};" \
        : "+f"((c)[0]), "+f"((c)[1]), "+f"((c)[2]), "+f"((c)[3]) \
        : "r"((a)[0]), "r"((a)[1]), "r"((a)[2]), "r"((a)[3]), "r"(b0v), "r"(b1v))

// ============================================================
// fp32 -> bf16 hi/lo split  (X rows and W rows)
// ============================================================
__global__ __launch_bounds__(256)
void convx_kernel(const float* __restrict__ q, const float* __restrict__ k,
                  const float* __restrict__ v)
{
    const int z = blockIdx.y;
    const float* src = (z == 0) ? q : (z == 1) ? k : v;
    __nv_bfloat16* dst = g_xcat + (size_t)z * ((size_t)ML_*1024);
    size_t e = ((size_t)blockIdx.x*256 + threadIdx.x) * 4;
    float4 x = *(const float4*)(src + e);
    size_t m = e >> 9, kk = e & 511;
    float xv[4] = {x.x, x.y, x.z, x.w};
    __nv_bfloat16 hi[4], lo[4];
#pragma unroll
    for (int i = 0; i < 4; i++) {
        hi[i] = __float2bfloat16(xv[i]);
        lo[i] = __float2bfloat16(xv[i] - __bfloat162float(hi[i]));
    }
    *(uint2*)(dst + m*1024 + kk)       = *(uint2*)hi;
    *(uint2*)(dst + m*1024 + 512 + kk) = *(uint2*)lo;
}

__global__ __launch_bounds__(256)
void convw_kernel(const float* __restrict__ wq, const float* __restrict__ wk,
                  const float* __restrict__ wv)
{
    const int z = blockIdx.y;
    const float* src = (z == 0) ? wq : (z == 1) ? wk : wv;
    __nv_bfloat16* dst = g_wcat + (size_t)z * ((size_t)F_*1024);
    size_t e = ((size_t)blockIdx.x*256 + threadIdx.x) * 4;
    float4 x = *(const float4*)(src + e);
    size_t m = e >> 9, kk = e & 511;
    float xv[4] = {x.x, x.y, x.z, x.w};
    __nv_bfloat16 hi[4], lo[4];
#pragma unroll
    for (int i = 0; i < 4; i++) {
        hi[i] = __float2bfloat16(xv[i]);
        lo[i] = __float2bfloat16(xv[i] - __bfloat162float(hi[i]));
    }
    *(uint2*)(dst + m*1024 + kk)       = *(uint2*)hi;
    *(uint2*)(dst + m*1024 + 512 + kk) = *(uint2*)lo;
}

// ============================================================
// HMMA projection GEMM: C = X @ W^T + b via bf16 split x3.
// CTA 128x128, 8 warps (4m x 2n), warp tile 32x64, k-chunk 64.
// smem tiles stride 72 bf16 (144B) -> conflict-free ldmatrix.
// grid (4, 128, 3); out layout (B,H,L,D)
// ============================================================
#define TS 72                       // smem tile stride (bf16)
#define TILE_E (128*TS)             // elems per tile
#define HM_SMEM (4*TILE_E*2)        // bytes: Ah, Al, Bh, Bl

__global__ __launch_bounds__(256, 2)
void hmma_proj_kernel(float* qd, float* kd, float* vd,
                      const float* __restrict__ bq,
                      const float* __restrict__ bk,
                      const float* __restrict__ bv)
{
    extern __shared__ __align__(16) char dsm[];
    __nv_bfloat16* Ah = (__nv_bfloat16*)dsm;
    __nv_bfloat16* Al = Ah + TILE_E;
    __nv_bfloat16* Bh = Ah + 2*TILE_E;
    __nv_bfloat16* Bl = Ah + 3*TILE_E;

    const int tid = threadIdx.x;
    const int lane = tid & 31, wid = tid >> 5;
    const int z = blockIdx.z;
    const int m0 = blockIdx.y * 128, n0 = blockIdx.x * 128;
    const int wm = (wid >> 1) * 32;       // warp m offset in tile
    const int wn = (wid & 1) * 64;        // warp n offset in tile

    const __nv_bfloat16* xc = g_xcat + (size_t)z * ((size_t)ML_*1024);
    const __nv_bfloat16* wc = g_wcat + (size_t)z * ((size_t)F_*1024);
    float* dst = (z == 0) ? qd : (z == 1) ? kd : vd;
    const float* bias = (z == 0) ? bq : (z == 1) ? bk : bv;

    float acc[2][8][4];
#pragma unroll
    for (int i = 0; i < 2; i++)
#pragma unroll
        for (int j = 0; j < 8; j++)
#pragma unroll
            for (int c = 0; c < 4; c++) acc[i][j][c] = 0.f;

    // ldmatrix per-lane base addresses (bytes)
    const int lrow = lane & 15, lhalf = lane >> 4;
    const uint32_t sAh = smem_u32(Ah), sAl = smem_u32(Al);
    const uint32_t sBh = smem_u32(Bh), sBl = smem_u32(Bl);
    uint32_t aoffH = sAh + (uint32_t)(((wm + lrow)*TS + lhalf*8) * 2);
    uint32_t aoffL = sAl + (uint32_t)(((wm + lrow)*TS + lhalf*8) * 2);
    uint32_t boffH[4], boffL[4];
#pragma unroll
    for (int nq = 0; nq < 4; nq++) {
        boffH[nq] = sBh + (uint32_t)(((wn + nq*16 + lrow)*TS + lhalf*8) * 2);
        boffL[nq] = sBl + (uint32_t)(((wn + nq*16 + lrow)*TS + lhalf*8) * 2);
    }

    for (int kc = 0; kc < 8; kc++) {
        __syncthreads();
#pragma unroll
        for (int it = 0; it < 4; it++) {
            int idx = tid + it*256;
            int row = idx >> 3, c8 = (idx & 7) << 3;
            const __nv_bfloat16* xr = xc + (size_t)(m0 + row)*1024 + kc*64 + c8;
            const __nv_bfloat16* wr = wc + (size_t)(n0 + row)*1024 + kc*64 + c8;
            *(uint4*)(Ah + row*TS + c8) = *(const uint4*)(xr);
            *(uint4*)(Al + row*TS + c8) = *(const uint4*)(xr + 512);
            *(uint4*)(Bh + row*TS + c8) = *(const uint4*)(wr);
            *(uint4*)(Bl + row*TS + c8) = *(const uint4*)(wr + 512);
        }
        __syncthreads();

#pragma unroll
        for (int kt = 0; kt < 4; kt++) {
            const uint32_t kb = kt * 32;   // 16 bf16 = 32 bytes
            uint32_t ah[2][4], al[2][4];
            LDSM4(ah[0], aoffH + kb);
            LDSM4(ah[1], aoffH + kb + 16*TS*2);   // second m16 tile: +16 rows
            LDSM4(al[0], aoffL + kb);
            LDSM4(al[1], aoffL + kb + 16*TS*2);
#pragma unroll
            for (int nq = 0; nq < 4; nq++) {
                uint32_t bh[4], bl[4];
                LDSM4(bh, boffH[nq] + kb);
                LDSM4(bl, boffL[nq] + kb);
#pragma unroll
                for (int mi = 0; mi < 2; mi++) {
                    MMA16816(acc[mi][nq*2],   ah[mi], bh[0], bh[2]);
                    MMA16816(acc[mi][nq*2+1], ah[mi], bh[1], bh[3]);
                    MMA16816(acc[mi][nq*2],   ah[mi], bl[0], bl[2]);
                    MMA16816(acc[mi][nq*2+1], ah[mi], bl[1], bl[3]);
                    MMA16816(acc[mi][nq*2],   al[mi], bh[0], bh[2]);
                    MMA16816(acc[mi][nq*2+1], al[mi], bh[1], bh[3]);
                }
            }
        }
    }

    // ---- epilogue ----
    const int r0 = lane >> 2, c0 = (lane & 3) << 1;
#pragma unroll
    for (int mi = 0; mi < 2; mi++) {
        int mA = m0 + wm + mi*16 + r0;
        int mB = mA + 8;
        int bA = mA >> 10, lA = mA & (L_-1);
        int bB = mB >> 10, lB = mB & (L_-1);
#pragma unroll
        for (int ni = 0; ni < 8; ni++) {
            int n = n0 + wn + ni*8 + c0;
            int h = n >> 6, d = n & 63;
            float b0v = bias[n], b1v = bias[n+1];
            float* pA = dst + ((size_t)(bA*H_ + h)*L_ + lA)*D_ + d;
            float* pB = dst + ((size_t)(bB*H_ + h)*L_ + lB)*D_ + d;
            *(float2*)pA = make_float2(acc[mi][ni][0] + b0v, acc[mi][ni][1] + b1v);
            *(float2*)pB = make_float2(acc[mi][ni][2] + b0v, acc[mi][ni][3] + b1v);
        }
    }
}

// ============================================================
// qk M kernel (fp32 f32x2, unchanged from passing build)
// ============================================================
__global__ __launch_bounds__(256, 2)
void qk_m3_kernel()
{
    __shared__ float Qs[64][130];
    __shared__ float Ks[2][8][130];
    const int tid = threadIdx.x;
    const int tx = tid & 15, ty = tid >> 4;
    const int bh = blockIdx.y;
    const int q0 = blockIdx.x * 128;
    const float* qp = g_q + (size_t)bh*L_*D_;
    const float* kp = g_k + (size_t)bh*L_*D_;

#pragma unroll
    for (int i = 0; i < 8; i++) {
        int idx = tid + i*256;
        int q = idx >> 4, dc = (idx & 15) << 2;
        float4 v = *(const float4*)(qp + (size_t)(q0 + q)*D_ + dc);
        int qo = ((q & 63) << 1) | (q >> 6);
        Qs[dc+0][qo] = v.x; Qs[dc+1][qo] = v.y;
        Qs[dc+2][qo] = v.z; Qs[dc+3][qo] = v.w;
    }

    const int kr  = tid >> 1;
    const int dc2 = (tid & 1) << 2;

    float rmax[8], rsum[8];
#pragma unroll
    for (int r2 = 0; r2 < 8; r2++) { rmax[r2] = -INF_F; rsum[r2] = 0.f; }
    u64 acc[4][8];

    float4 rk = *(const float4*)(kp + (size_t)kr*D_ + dc2);
#define KST(bsel) do { \
    Ks[bsel][dc2+0][kr] = rk.x; Ks[bsel][dc2+1][kr] = rk.y; \
    Ks[bsel][dc2+2][kr] = rk.z; Ks[bsel][dc2+3][kr] = rk.w; } while(0)
    KST(0);
    __syncthreads();

    for (int c = 0; c < 64; c++) {
        if ((c & 7) == 0) {
#pragma unroll
            for (int i = 0; i < 4; i++)
#pragma unroll
                for (int j = 0; j < 8; j++) acc[i][j] = 0ULL;
        }
        if (c < 63) {
            int ktn = ((c+1) >> 3) << 7;
            int d0n = ((c+1) & 7) << 3;
            rk = *(const float4*)(kp + (size_t)(ktn + kr)*D_ + d0n + dc2);
        }
        const int bsel = c & 1;
        const int d0 = (c & 7) << 3;
#pragma unroll
        for (int dd = 0; dd < 8; dd++) {
            const float* qrow = &Qs[d0+dd][ty << 3];
            u64 av[4];
            av[0] = *(const u64*)(qrow);
            av[1] = *(const u64*)(qrow + 2);
            av[2] = *(const u64*)(qrow + 4);
            av[3] = *(const u64*)(qrow + 6);
            const float* krow = &Ks[bsel][dd][tx << 3];
            u64 bv[8];
#pragma unroll
            for (int j2 = 0; j2 < 4; j2++) {
                float2 b2 = *(const float2*)(krow + (j2 << 1));
                bv[j2*2]   = dup2(b2.x);
                bv[j2*2+1] = dup2(b2.y);
            }
#pragma unroll
            for (int i = 0; i < 4; i++)
#pragma unroll
                for (int j = 0; j < 8; j++)
                    fma2(acc[i][j], av[i], bv[j]);
        }
        if ((c & 7) == 7) {
#pragma unroll
            for (int i = 0; i < 4; i++) {
                float mLo = -INF_F, mHi = -INF_F, sLo = 0.f, sHi = 0.f;
#pragma unroll
                for (int j = 0; j < 8; j++) {
                    float2 t2 = unpk(acc[i][j]);
                    mLo = fmaxf(mLo, t2.x); sLo += t2.x;
                    mHi = fmaxf(mHi, t2.y); sHi += t2.y;
                }
                rmax[i]   = fmaxf(rmax[i],   mLo); rsum[i]   += sLo;
                rmax[i+4] = fmaxf(rmax[i+4], mHi); rsum[i+4] += sHi;
            }
        }
        if (c < 63) KST((c+1) & 1);
        __syncthreads();
    }
#undef KST

#pragma unroll
    for (int r2 = 0; r2 < 8; r2++) {
        float m = rmax[r2], s = rsum[r2];
#pragma unroll
        for (int off = 8; off; off >>= 1) {
            m = fmaxf(m, __shfl_xor_sync(0xffffffffu, m, off));
            s += __shfl_xor_sync(0xffffffffu, s, off);
        }
        rmax[r2] = m; rsum[r2] = s;
    }
    if (tx == 0) {
#pragma unroll
        for (int r2 = 0; r2 < 8; r2++) {
            int row = q0 + (ty << 2) + (r2 & 3) + ((r2 >> 2) << 6);
            g_M[(size_t)bh*L_ + row] = rmax[r2] - rsum[r2] * (1.0f/L_);
        }
    }
}

// ============================================================
__global__ __launch_bounds__(256)
void topk_warp_kernel()
{
    const int warp = threadIdx.x >> 5, lane = threadIdx.x & 31;
    const int bh = blockIdx.x * 8 + warp;
    const float* Mp = g_M + (size_t)bh*L_;
    float v[32];
#pragma unroll
    for (int j = 0; j < 32; j++) v[j] = Mp[j*32 + lane];

    for (int it = 0; it < U_; it++) {
        float bv = v[0]; int bj = 0;
#pragma unroll
        for (int j = 1; j < 32; j++)
            if (v[j] > bv) { bv = v[j]; bj = j; }
        int bk = bj*32 + lane;
#pragma unroll
        for (int off = 16; off; off >>= 1) {
            float ov = __shfl_xor_sync(0xffffffffu, bv, off);
            int   ok = __shfl_xor_sync(0xffffffffu, bk, off);
            if (ov > bv || (ov == bv && ok < bk)) { bv = ov; bk = ok; }
        }
        if (lane == 0) g_idx[bh*U_ + it] = bk;
        int cj = bk >> 5;
        bool mine = ((bk & 31) == lane);
#pragma unroll
        for (int j = 0; j < 32; j++)
            if (mine && j == cj) v[j] = -INF_F;
    }
}

// ============================================================
__global__ __launch_bounds__(256)
void vmean_kernel()
{
    const int bh = blockIdx.x, tid = threadIdx.x;
    const int d = tid & 63, part = tid >> 6;
    const float* vp = g_v + (size_t)bh*L_*D_;
    float acc = 0.f;
    for (int l = part*256; l < part*256 + 256; l++)
        acc += vp[(size_t)l*D_ + d];
    __shared__ float red[4][64];
    red[part][d] = acc;
    __syncthreads();
    if (tid < 64)
        g_vm[bh*64 + tid] =
            (red[0][tid] + red[1][tid] + red[2][tid] + red[3][tid]) * (1.0f/L_);
}

__global__ void zero_kernel()
{
    int t = blockIdx.x*256 + threadIdx.x;
    if (t < B_*L_) g_flag[t] = 0;
    if (t < B_)    g_cnt[t]  = 0;
}

__global__ void compact_kernel()
{
    int t = blockIdx.x*256 + threadIdx.x;
    if (t >= BH_*U_) return;
    int bh = t / U_;
    int b  = bh >> 3;
    int row = g_idx[t];
    if (atomicExch(&g_flag[b*L_ + row], 1) == 0) {
        int p = atomicAdd(&g_cnt[b], 1);
        g_rows[b*L_ + p] = row;
    }
}

__global__ __launch_bounds__(256)
void x2init_kernel()
{
    const int b = blockIdx.x, t = blockIdx.y, tid = threadIdx.x;
    __shared__ float vms[F_];
    for (int f = tid; f < F_; f += 256)
        vms[f] = g_vm[(b*H_ + (f >> 6))*64 + (f & 63)];
    __syncthreads();
    const int cnt = g_cnt[b];
    int hiR = t*128 + 128; if (hiR > cnt) hiR = cnt;
    for (int ri = t*128; ri < hiR; ri++) {
        int l = g_rows[b*L_ + ri];
        float* p = g_x2 + ((size_t)b*L_ + l)*F_;
        p[tid]       = vms[tid];
        p[tid + 256] = vms[tid + 256];
    }
}

// ============================================================
__global__ __launch_bounds__(256)
void sp_scores_kernel(const int* __restrict__ mask)
{
    __shared__ float qs[U_][64];
    __shared__ float Ks[128][68];
    __shared__ int   sidx[U_];
    const int bh = blockIdx.x, tid = threadIdx.x;
    const int b = bh >> 3;
    const int kt0 = blockIdx.y << 7;
    const float* qp = g_q + (size_t)bh*L_*D_;
    const float* kp = g_k + (size_t)bh*L_*D_;
    float* scp = g_sc + (size_t)bh*U_*L_;
    const int* mrow = mask + b*L_;

    if (tid < U_) sidx[tid] = g_idx[bh*U_ + tid];
    __syncthreads();
    for (int i = tid; i < U_*16; i += 256) {
        int u = i >> 4, dc = (i & 15) << 2;
        *(float4*)&qs[u][dc] = *(const float4*)(qp + (size_t)sidx[u]*D_ + dc);
    }
    for (int i = tid; i < 128*16; i += 256) {
        int k = i >> 4, dc = (i & 15) << 2;
        *(float4*)&Ks[k][dc] = *(const float4*)(kp + (size_t)(kt0 + k)*D_ + dc);
    }
    __syncthreads();

    for (int p = tid; p < U_*128; p += 256) {
        int u = p >> 7, kk = p & 127;
        float s = 0.f;
#pragma unroll
        for (int dc = 0; dc < 64; dc += 4) {
            float4 a = *(const float4*)&qs[u][dc];
            float4 c = *(const float4*)&Ks[kk][dc];
            s += a.x*c.x + a.y*c.y + a.z*c.z + a.w*c.w;
        }
        int k = kt0 + kk;
        s *= 0.125f;
        if (mrow[k] == 0) s = -INF_F;
        scp[(size_t)u*L_ + k] = s;
    }
}

__global__ __launch_bounds__(256)
void sp_softmax_kernel()
{
    const int bh = blockIdx.x, tid = threadIdx.x;
    float* scp = g_sc + (size_t)bh*U_*L_;
    const int wid = tid >> 5, lane = tid & 31;
    for (int u = wid; u < U_; u += 8) {
        float mx = -INF_F;
        for (int k = lane; k < L_; k += 32)
            mx = fmaxf(mx, scp[(size_t)u*L_ + k]);
#pragma unroll
        for (int off = 16; off; off >>= 1)
            mx = fmaxf(mx, __shfl_xor_sync(0xffffffffu, mx, off));
        float sm = 0.f;
        for (int k = lane; k < L_; k += 32) {
            float s = scp[(size_t)u*L_ + k];
            sm += (s == -INF_F) ? 0.f : expf(s - mx);
        }
#pragma unroll
        for (int off = 16; off; off >>= 1)
            sm += __shfl_xor_sync(0xffffffffu, sm, off);
        float inv = (sm > 0.f) ? 1.0f / sm : 0.f;
        for (int k = lane; k < L_; k += 32) {
            float s = scp[(size_t)u*L_ + k];
            float pv = (s == -INF_F || mx == -INF_F) ? 0.f : expf(s - mx) * inv;
            scp[(size_t)u*L_ + k] = pv;
        }
    }
}

__global__ __launch_bounds__(256)
void sp_ctx_kernel()
{
    __shared__ float ps[U_][64];
    __shared__ float cb[U_][64];
    __shared__ int   sidx[U_];
    const int bh = blockIdx.x, tid = threadIdx.x;
    const int b = bh >> 3, h = bh & 7;
    const float* vp = g_v + (size_t)bh*L_*D_;
    const float* scp = g_sc + (size_t)bh*U_*L_;
    if (tid < U_) sidx[tid] = g_idx[bh*U_ + tid];

    const int d = tid & 63, part = tid >> 6;
    float acc[U_];
#pragma unroll
    for (int u = 0; u < U_; u++) acc[u] = 0.f;

    for (int kt = 0; kt < L_; kt += 64) {
        __syncthreads();
        for (int i = tid; i < U_*64; i += 256) {
            int u = i >> 6, kk = i & 63;
            ps[u][kk] = scp[(size_t)u*L_ + kt + kk];
        }
        __syncthreads();
        for (int kk = part*16; kk < part*16 + 16; kk++) {
            float v = vp[(size_t)(kt + kk)*D_ + d];
#pragma unroll
            for (int u = 0; u < U_; u++)
                acc[u] += ps[u][kk] * v;
        }
    }
    __syncthreads();
    for (int p2 = 0; p2 < 4; p2++) {
        if (part == p2) {
#pragma unroll
            for (int u = 0; u < U_; u++) {
                if (p2 == 0) cb[u][d] = acc[u];
                else         cb[u][d] += acc[u];
            }
        }
        __syncthreads();
    }
    float* x2 = g_x2 + (size_t)b*L_*F_ + h*D_;
    for (int i = tid; i < U_*64; i += 256) {
        int u = i >> 6, dd = i & 63;
        x2[(size_t)sidx[u]*F_ + dd] = cb[u][dd];
    }
}

// ============================================================
__global__ __launch_bounds__(256)
void mean_out_kernel(const float* __restrict__ Wo, const float* __restrict__ bo)
{
    const int b = blockIdx.x, tid = threadIdx.x;
    __shared__ float vms[F_];
    for (int f = tid; f < F_; f += 256)
        vms[f] = g_vm[(b*H_ + (f >> 6))*64 + (f & 63)];
    __syncthreads();
    for (int n = tid; n < F_; n += 256) {
        float s = bo[n];
        const float* w = Wo + (size_t)n*F_;
        for (int f = 0; f < F_; f += 4) {
            float4 wv = *(const float4*)(w + f);
            s += vms[f]*wv.x + vms[f+1]*wv.y + vms[f+2]*wv.z + vms[f+3]*wv.w;
        }
        g_om[b*F_ + n] = s;
    }
}

__global__ __launch_bounds__(256)
void bcast_kernel(float* __restrict__ out)
{
    const int b = blockIdx.x, l0 = blockIdx.y << 3, tid = threadIdx.x;
    __shared__ float om[F_];
    for (int f = tid; f < F_; f += 256) om[f] = g_om[b*F_ + f];
    __syncthreads();
    float2 v = *(const float2*)&om[tid*2];
    float* base = out + ((size_t)b*L_ + l0)*F_;
#pragma unroll
    for (int rr = 0; rr < 8; rr++)
        *(float2*)(base + (size_t)rr*F_ + tid*2) = v;
}

// ============================================================
__global__ __launch_bounds__(256, 2)
void gemm_rows_kernel(const float* __restrict__ W,
                      const float* __restrict__ bias,
                      float* __restrict__ out)
{
    const int b = blockIdx.y / 3;
    const int t = blockIdx.y % 3;
    const int cnt = g_cnt[b];
    if (t * 128 >= cnt) return;

    __shared__ __align__(16) float As[2][16][132];
    __shared__ __align__(16) float Bs[2][16][132];
    __shared__ int rows_s[128];

    const int tid = threadIdx.x;
    if (tid < 128) {
        int gi = t*128 + tid;
        rows_s[tid] = (gi < cnt) ? g_rows[b*L_ + gi] : g_rows[b*L_];
    }
    __syncthreads();

    const float* X = g_x2 + (size_t)b*L_*F_;
    const int tx = tid & 15, ty = tid >> 4;
    const int n0 = blockIdx.x * 128;
    const int r  = tid >> 2;
    const int kc = (tid & 3) << 2;
    const int mo = r << 1;
    const int l0r = rows_s[r], l1r = rows_s[r + 64];

    u64 acc[4][8];
#pragma unroll
    for (int i = 0; i < 4; i++)
#pragma unroll
        for (int j = 0; j < 8; j++) acc[i][j] = 0ULL;

    float4 ra0, ra1, rb0, rb1;
    ra0 = *(const float4*)(X + (size_t)l0r*F_ + kc);
    ra1 = *(const float4*)(X + (size_t)l1r*F_ + kc);
    rb0 = *(const float4*)(W + (size_t)(n0 + r)*F_ + kc);
    rb1 = *(const float4*)(W + (size_t)(n0 + r + 64)*F_ + kc);

#define GSTORE(bsel) do { \
    As[bsel][kc+0][mo]   = ra0.x; As[bsel][kc+1][mo]   = ra0.y; \
    As[bsel][kc+2][mo]   = ra0.z; As[bsel][kc+3][mo]   = ra0.w; \
    As[bsel][kc+0][mo+1] = ra1.x; As[bsel][kc+1][mo+1] = ra1.y; \
    As[bsel][kc+2][mo+1] = ra1.z; As[bsel][kc+3][mo+1] = ra1.w; \
    Bs[bsel][kc+0][r]    = rb0.x; Bs[bsel][kc+1][r]    = rb0.y; \
    Bs[bsel][kc+2][r]    = rb0.z; Bs[bsel][kc+3][r]    = rb0.w; \
    Bs[bsel][kc+0][r+64] = rb1.x; Bs[bsel][kc+1][r+64] = rb1.y; \
    Bs[bsel][kc+2][r+64] = rb1.z; Bs[bsel][kc+3][r+64] = rb1.w; } while(0)

    GSTORE(0);
    __syncthreads();

    for (int c = 0; c < 32; c++) {
        if (c < 31) {
            int kb = (c + 1) << 4;
            ra0 = *(const float4*)(X + (size_t)l0r*F_ + kb + kc);
            ra1 = *(const float4*)(X + (size_t)l1r*F_ + kb + kc);
            rb0 = *(const float4*)(W + (size_t)(n0 + r)*F_ + kb + kc);
            rb1 = *(const float4*)(W + (size_t)(n0 + r + 64)*F_ + kb + kc);
        }
        const int bsel = c & 1;
#pragma unroll
        for (int kk = 0; kk < 16; kk++) {
            ulonglong2 a01 = *(const ulonglong2*)&As[bsel][kk][ty << 3];
            ulonglong2 a23 = *(const ulonglong2*)&As[bsel][kk][(ty << 3) + 4];
            float4 b0 = *(const float4*)&Bs[bsel][kk][tx << 3];
            float4 b1 = *(const float4*)&Bs[bsel][kk][(tx << 3) + 4];
            u64 av[4] = {a01.x, a01.y, a23.x, a23.y};
            u64 bv[8] = {dup2(b0.x), dup2(b0.y), dup2(b0.z), dup2(b0.w),
                         dup2(b1.x), dup2(b1.y), dup2(b1.z), dup2(b1.w)};
#pragma unroll
            for (int i = 0; i < 4; i++)
#pragma unroll
                for (int j = 0; j < 8; j++)
                    fma2(acc[i][j], av[i], bv[j]);
        }
        if (c < 31) GSTORE((c + 1) & 1);
        __syncthreads();
    }
#undef GSTORE

    const int nb = n0 + (tx << 3);
    float bb[8];
#pragma unroll
    for (int j = 0; j < 8; j++) bb[j] = bias[nb + j];

#pragma unroll
    for (int i = 0; i < 4; i++) {
        float lo[8], hi[8];
#pragma unroll
        for (int j = 0; j < 8; j++) {
            float2 tt = unpk(acc[i][j]);
            lo[j] = tt.x + bb[j];
            hi[j] = tt.y + bb[j];
        }
        {
            int l = rows_s[(ty << 2) + i];
            float* p = out + ((size_t)b*L_ + l)*F_ + nb;
            *(float4*)p     = make_float4(lo[0], lo[1], lo[2], lo[3]);
            *(float4*)(p+4) = make_float4(lo[4], lo[5], lo[6], lo[7]);
        }
        {
            int l = rows_s[(ty << 2) + i + 64];
            float* p = out + ((size_t)b*L_ + l)*F_ + nb;
            *(float4*)p     = make_float4(hi[0], hi[1], hi[2], hi[3]);
            *(float4*)(p+4) = make_float4(hi[4], hi[5], hi[6], hi[7]);
        }
    }
}

// ============================================================
extern "C" void kernel_launch(void* const* d_in, const int* in_sizes, int n_in,
                              void* d_out, int out_size)
{
    const float* query = (const float*)d_in[0];
    const float* key   = (const float*)d_in[1];
    const float* value = (const float*)d_in[2];
    const int*   mask  = (const int*)  d_in[3];
    const float* Wq = (const float*)d_in[4];
    const float* bq = (const float*)d_in[5];
    const float* Wk = (const float*)d_in[6];
    const float* bk = (const float*)d_in[7];
    const float* Wv = (const float*)d_in[8];
    const float* bv = (const float*)d_in[9];
    const float* Wo = (const float*)d_in[10];
    const float* bo = (const float*)d_in[11];
    float* out = (float*)d_out;

    float *qd, *kd, *vd;
    cudaGetSymbolAddress((void**)&qd, g_q);
    cudaGetSymbolAddress((void**)&kd, g_k);
    cudaGetSymbolAddress((void**)&vd, g_v);

    cudaFuncSetAttribute(hmma_proj_kernel,
                         cudaFuncAttributeMaxDynamicSharedMemorySize, HM_SMEM);

    zero_kernel<<<64, 256>>>();
    convx_kernel<<<dim3((ML_*F_/4)/256, 3), 256>>>(query, key, value);
    convw_kernel<<<dim3((F_*F_/4)/256, 3), 256>>>(Wq, Wk, Wv);

    hmma_proj_kernel<<<dim3(F_/128, ML_/128, 3), 256, HM_SMEM>>>(qd, kd, vd, bq, bk, bv);

    dim3 gm(L_/128, BH_);
    qk_m3_kernel<<<gm, 256>>>();

    topk_warp_kernel<<<BH_/8, 256>>>();
    vmean_kernel<<<BH_, 256>>>();
    compact_kernel<<<(BH_*U_ + 255)/256, 256>>>();
    x2init_kernel<<<dim3(B_, 3), 256>>>();

    sp_scores_kernel<<<dim3(BH_, 8), 256>>>(mask);
    sp_softmax_kernel<<<BH_, 256>>>();
    sp_ctx_kernel<<<BH_, 256>>>();

    mean_out_kernel<<<B_, 256>>>(Wo, bo);
    bcast_kernel<<<dim3(B_, L_/8), 256>>>(out);
    gemm_rows_kernel<<<dim3(F_/128, B_*3), 256>>>(Wo, bo, out);
}

// round 8
// speedup vs baseline: 2.1841x; 1.2789x over previous
#include <cuda_runtime.h>
#include <cuda_bf16.h>
#include <cstdint>

typedef unsigned long long u64;

#define B_  16
#define L_  1024
#define F_  512
#define H_  8
#define D_  64
#define U_  35
#define BH_ (B_*H_)
#define ML_ (B_*L_)

#define INF_F __int_as_float(0x7f800000)

// -------- device scratch --------
__device__ float g_q[(size_t)BH_*L_*D_];
__device__ float g_k[(size_t)BH_*L_*D_];
__device__ float g_v[(size_t)BH_*L_*D_];
__device__ float g_M[(size_t)BH_*L_];
__device__ int   g_idx[BH_*U_];
__device__ float g_x2[(size_t)ML_*F_];
__device__ float g_sc[(size_t)BH_*U_*L_];
__device__ float g_vm[BH_*D_];
__device__ float g_om[B_*F_];
__device__ int   g_flag[B_*L_];
__device__ int   g_cnt[B_];
__device__ int   g_rows[B_*L_];
__device__ __nv_bfloat16 g_xcat[3ULL*ML_*1024];  // [hi(512)|lo(512)] per row
__device__ __nv_bfloat16 g_wcat[3ULL*F_*1024];
__device__ __nv_bfloat16 g_qs[(size_t)BH_*L_*128];  // q split [hi(64)|lo(64)]
__device__ __nv_bfloat16 g_ks[(size_t)BH_*L_*128];  // k split

// -------- f32x2 helpers --------
__device__ __forceinline__ void fma2(u64 &acc, u64 a, u64 b) {
    asm("fma.rn.f32x2 %0, %1, %2, %0;" : "+l"(acc) : "l"(a), "l"(b));
}
__device__ __forceinline__ u64 dup2(float v) {
    u64 r; asm("mov.b64 %0, {%1, %1};" : "=l"(r) : "f"(v)); return r;
}
__device__ __forceinline__ float2 unpk(u64 v) {
    float2 r; asm("mov.b64 {%0, %1}, %2;" : "=f"(r.x), "=f"(r.y) : "l"(v)); return r;
}

// -------- mma.sync helpers (baseline PTX, sm_80+) --------
__device__ __forceinline__ uint32_t smem_u32(const void* p) {
    uint32_t a;
    asm("{ .reg .u64 t; cvta.to.shared.u64 t, %1; cvt.u32.u64 %0, t; }" : "=r"(a) : "l"(p));
    return a;
}
#define LDSM4(r, addr) \
    asm volatile("ldmatrix.sync.aligned.m8n8.x4.shared.b16 {%0,%1,%2,%3}, [%4];" \
        : "=r"((r)[0]), "=r"((r)[1]), "=r"((r)[2]), "=r"((r)[3]) : "r"(addr))
#define MMA16816(c, a, b0v, b1v) \
    asm volatile("mma.sync.aligned.m16n8k16.row.col.f32.bf16.bf16.f32 " \
        "{%0,%1,%2,%3}, {%4,%5,%6,%7}, {%8,%9}, {%0,%1,%2,%3};" \
        : "+f"((c)[0]), "+f"((c)[1]), "+f"((c)[2]), "+f"((c)[3]) \
        : "r"((a)[0]), "r"((a)[1]), "r"((a)[2]), "r"((a)[3]), "r"(b0v), "r"(b1v))

__device__ __forceinline__ uint32_t pack_bf2(float x, float y) {
    __nv_bfloat162 t;
    t.x = __float2bfloat16(x);
    t.y = __float2bfloat16(y);
    return *(uint32_t*)&t;
}

// ============================================================
// fp32 -> bf16 hi/lo split  (X rows and W rows)
// ============================================================
__global__ __launch_bounds__(256)
void convx_kernel(const float* __restrict__ q, const float* __restrict__ k,
                  const float* __restrict__ v)
{
    const int z = blockIdx.y;
    const float* src = (z == 0) ? q : (z == 1) ? k : v;
    __nv_bfloat16* dst = g_xcat + (size_t)z * ((size_t)ML_*1024);
    size_t e = ((size_t)blockIdx.x*256 + threadIdx.x) * 4;
    float4 x = *(const float4*)(src + e);
    size_t m = e >> 9, kk = e & 511;
    float xv[4] = {x.x, x.y, x.z, x.w};
    __nv_bfloat16 hi[4], lo[4];
#pragma unroll
    for (int i = 0; i < 4; i++) {
        hi[i] = __float2bfloat16(xv[i]);
        lo[i] = __float2bfloat16(xv[i] - __bfloat162float(hi[i]));
    }
    *(uint2*)(dst + m*1024 + kk)       = *(uint2*)hi;
    *(uint2*)(dst + m*1024 + 512 + kk) = *(uint2*)lo;
}

__global__ __launch_bounds__(256)
void convw_kernel(const float* __restrict__ wq, const float* __restrict__ wk,
                  const float* __restrict__ wv)
{
    const int z = blockIdx.y;
    const float* src = (z == 0) ? wq : (z == 1) ? wk : wv;
    __nv_bfloat16* dst = g_wcat + (size_t)z * ((size_t)F_*1024);
    size_t e = ((size_t)blockIdx.x*256 + threadIdx.x) * 4;
    float4 x = *(const float4*)(src + e);
    size_t m = e >> 9, kk = e & 511;
    float xv[4] = {x.x, x.y, x.z, x.w};
    __nv_bfloat16 hi[4], lo[4];
#pragma unroll
    for (int i = 0; i < 4; i++) {
        hi[i] = __float2bfloat16(xv[i]);
        lo[i] = __float2bfloat16(xv[i] - __bfloat162float(hi[i]));
    }
    *(uint2*)(dst + m*1024 + kk)       = *(uint2*)hi;
    *(uint2*)(dst + m*1024 + 512 + kk) = *(uint2*)lo;
}

// ============================================================
// HMMA projection GEMM: C = X @ W^T + b via bf16 split x3.
// CTA 128x128, 8 warps (4m x 2n), warp tile 32x64, k-chunk 64.
// For z<2 the epilogue also emits the bf16 hi/lo split of the
// result rows into g_qs/g_ks for the qk_hmma kernel.
// ============================================================
#define TS 72                       // smem tile stride (bf16)
#define TILE_E (128*TS)             // elems per tile
#define HM_SMEM (4*TILE_E*2)        // bytes: Ah, Al, Bh, Bl

__global__ __launch_bounds__(256, 2)
void hmma_proj_kernel(float* qd, float* kd, float* vd,
                      const float* __restrict__ bq,
                      const float* __restrict__ bk,
                      const float* __restrict__ bv)
{
    extern __shared__ __align__(16) char dsm[];
    __nv_bfloat16* Ah = (__nv_bfloat16*)dsm;
    __nv_bfloat16* Al = Ah + TILE_E;
    __nv_bfloat16* Bh = Ah + 2*TILE_E;
    __nv_bfloat16* Bl = Ah + 3*TILE_E;

    const int tid = threadIdx.x;
    const int lane = tid & 31, wid = tid >> 5;
    const int z = blockIdx.z;
    const int m0 = blockIdx.y * 128, n0 = blockIdx.x * 128;
    const int wm = (wid >> 1) * 32;
    const int wn = (wid & 1) * 64;

    const __nv_bfloat16* xc = g_xcat + (size_t)z * ((size_t)ML_*1024);
    const __nv_bfloat16* wc = g_wcat + (size_t)z * ((size_t)F_*1024);
    float* dst = (z == 0) ? qd : (z == 1) ? kd : vd;
    const float* bias = (z == 0) ? bq : (z == 1) ? bk : bv;

    float acc[2][8][4];
#pragma unroll
    for (int i = 0; i < 2; i++)
#pragma unroll
        for (int j = 0; j < 8; j++)
#pragma unroll
            for (int c = 0; c < 4; c++) acc[i][j][c] = 0.f;

    const int lrow = lane & 15, lhalf = lane >> 4;
    const uint32_t sAh = smem_u32(Ah), sAl = smem_u32(Al);
    const uint32_t sBh = smem_u32(Bh), sBl = smem_u32(Bl);
    uint32_t aoffH = sAh + (uint32_t)(((wm + lrow)*TS + lhalf*8) * 2);
    uint32_t aoffL = sAl + (uint32_t)(((wm + lrow)*TS + lhalf*8) * 2);
    uint32_t boffH[4], boffL[4];
#pragma unroll
    for (int nq = 0; nq < 4; nq++) {
        boffH[nq] = sBh + (uint32_t)(((wn + nq*16 + lrow)*TS + lhalf*8) * 2);
        boffL[nq] = sBl + (uint32_t)(((wn + nq*16 + lrow)*TS + lhalf*8) * 2);
    }

    for (int kc = 0; kc < 8; kc++) {
        __syncthreads();
#pragma unroll
        for (int it = 0; it < 4; it++) {
            int idx = tid + it*256;
            int row = idx >> 3, c8 = (idx & 7) << 3;
            const __nv_bfloat16* xr = xc + (size_t)(m0 + row)*1024 + kc*64 + c8;
            const __nv_bfloat16* wr = wc + (size_t)(n0 + row)*1024 + kc*64 + c8;
            *(uint4*)(Ah + row*TS + c8) = *(const uint4*)(xr);
            *(uint4*)(Al + row*TS + c8) = *(const uint4*)(xr + 512);
            *(uint4*)(Bh + row*TS + c8) = *(const uint4*)(wr);
            *(uint4*)(Bl + row*TS + c8) = *(const uint4*)(wr + 512);
        }
        __syncthreads();

#pragma unroll
        for (int kt = 0; kt < 4; kt++) {
            const uint32_t kb = kt * 32;
            uint32_t ah[2][4], al[2][4];
            LDSM4(ah[0], aoffH + kb);
            LDSM4(ah[1], aoffH + kb + 16*TS*2);
            LDSM4(al[0], aoffL + kb);
            LDSM4(al[1], aoffL + kb + 16*TS*2);
#pragma unroll
            for (int nq = 0; nq < 4; nq++) {
                uint32_t bh[4], bl[4];
                LDSM4(bh, boffH[nq] + kb);
                LDSM4(bl, boffL[nq] + kb);
#pragma unroll
                for (int mi = 0; mi < 2; mi++) {
                    MMA16816(acc[mi][nq*2],   ah[mi], bh[0], bh[2]);
                    MMA16816(acc[mi][nq*2+1], ah[mi], bh[1], bh[3]);
                    MMA16816(acc[mi][nq*2],   ah[mi], bl[0], bl[2]);
                    MMA16816(acc[mi][nq*2+1], ah[mi], bl[1], bl[3]);
                    MMA16816(acc[mi][nq*2],   al[mi], bh[0], bh[2]);
                    MMA16816(acc[mi][nq*2+1], al[mi], bh[1], bh[3]);
                }
            }
        }
    }

    // ---- epilogue: fp32 out + (z<2) bf16 hi/lo split out ----
    __nv_bfloat16* sp = (z == 0) ? g_qs : g_ks;
    const int r0 = lane >> 2, c0 = (lane & 3) << 1;
#pragma unroll
    for (int mi = 0; mi < 2; mi++) {
        int mA = m0 + wm + mi*16 + r0;
        int mB = mA + 8;
        int bA = mA >> 10, lA = mA & (L_-1);
        int bB = mB >> 10, lB = mB & (L_-1);
#pragma unroll
        for (int ni = 0; ni < 8; ni++) {
            int n = n0 + wn + ni*8 + c0;
            int h = n >> 6, d = n & 63;
            float b0v = bias[n], b1v = bias[n+1];
            float vA0 = acc[mi][ni][0] + b0v, vA1 = acc[mi][ni][1] + b1v;
            float vB0 = acc[mi][ni][2] + b0v, vB1 = acc[mi][ni][3] + b1v;
            size_t rowA = (size_t)(bA*H_ + h)*L_ + lA;
            size_t rowB = (size_t)(bB*H_ + h)*L_ + lB;
            *(float2*)(dst + rowA*D_ + d) = make_float2(vA0, vA1);
            *(float2*)(dst + rowB*D_ + d) = make_float2(vB0, vB1);
            if (z < 2) {
                float hA0 = __bfloat162float(__float2bfloat16(vA0));
                float hA1 = __bfloat162float(__float2bfloat16(vA1));
                float hB0 = __bfloat162float(__float2bfloat16(vB0));
                float hB1 = __bfloat162float(__float2bfloat16(vB1));
                __nv_bfloat16* pA = sp + rowA*128 + d;
                __nv_bfloat16* pB = sp + rowB*128 + d;
                *(uint32_t*)pA        = pack_bf2(vA0, vA1);
                *(uint32_t*)(pA + 64) = pack_bf2(vA0 - hA0, vA1 - hA1);
                *(uint32_t*)pB        = pack_bf2(vB0, vB1);
                *(uint32_t*)(pB + 64) = pack_bf2(vB0 - hB0, vB1 - hB1);
            }
        }
    }
}

// ============================================================
// qk M kernel via HMMA split-bf16:
// M[b,h,q] = max_k(q.k) - mean_k(q.k), never materializing S.
// grid (L/128, BH), 8 warps (4m x 2n), Q tile resident.
// ============================================================
#define QK_SMEM (4*TILE_E*2)

__global__ __launch_bounds__(256, 2)
void qk_hmma_kernel()
{
    extern __shared__ __align__(16) char dsm[];
    __nv_bfloat16* Qh = (__nv_bfloat16*)dsm;
    __nv_bfloat16* Ql = Qh + TILE_E;
    __nv_bfloat16* Kh = Qh + 2*TILE_E;
    __nv_bfloat16* Kl = Qh + 3*TILE_E;
    __shared__ float redmax[2][128];
    __shared__ float redsum[2][128];

    const int tid = threadIdx.x;
    const int lane = tid & 31, wid = tid >> 5;
    const int bh = blockIdx.y, q0 = blockIdx.x * 128;
    const int wm = (wid >> 1) * 32, wn = (wid & 1) * 64;

    const __nv_bfloat16* qs = g_qs + (size_t)bh*L_*128;
    const __nv_bfloat16* ks = g_ks + (size_t)bh*L_*128;

    // Q tile resident (128 rows x [hi64|lo64])
#pragma unroll
    for (int it = 0; it < 4; it++) {
        int idx = tid + it*256;
        int row = idx >> 3, c8 = (idx & 7) << 3;
        const __nv_bfloat16* src = qs + (size_t)(q0 + row)*128 + c8;
        *(uint4*)(Qh + row*TS + c8) = *(const uint4*)(src);
        *(uint4*)(Ql + row*TS + c8) = *(const uint4*)(src + 64);
    }

    const int lrow = lane & 15, lhalf = lane >> 4;
    const uint32_t sQh = smem_u32(Qh), sQl = smem_u32(Ql);
    const uint32_t sKh = smem_u32(Kh), sKl = smem_u32(Kl);
    uint32_t aoffH = sQh + (uint32_t)(((wm + lrow)*TS + lhalf*8) * 2);
    uint32_t aoffL = sQl + (uint32_t)(((wm + lrow)*TS + lhalf*8) * 2);
    uint32_t boffH[4], boffL[4];
#pragma unroll
    for (int nq = 0; nq < 4; nq++) {
        boffH[nq] = sKh + (uint32_t)(((wn + nq*16 + lrow)*TS + lhalf*8) * 2);
        boffL[nq] = sKl + (uint32_t)(((wn + nq*16 + lrow)*TS + lhalf*8) * 2);
    }

    float rmax_[2][2], rsum_[2][2];
#pragma unroll
    for (int i = 0; i < 2; i++)
#pragma unroll
        for (int j = 0; j < 2; j++) { rmax_[i][j] = -INF_F; rsum_[i][j] = 0.f; }

    for (int kt = 0; kt < 8; kt++) {
        __syncthreads();
#pragma unroll
        for (int it = 0; it < 4; it++) {
            int idx = tid + it*256;
            int row = idx >> 3, c8 = (idx & 7) << 3;
            const __nv_bfloat16* src = ks + (size_t)(kt*128 + row)*128 + c8;
            *(uint4*)(Kh + row*TS + c8) = *(const uint4*)(src);
            *(uint4*)(Kl + row*TS + c8) = *(const uint4*)(src + 64);
        }
        __syncthreads();

        float acc[2][8][4];
#pragma unroll
        for (int i = 0; i < 2; i++)
#pragma unroll
            for (int j = 0; j < 8; j++)
#pragma unroll
                for (int c = 0; c < 4; c++) acc[i][j][c] = 0.f;

#pragma unroll
        for (int k16 = 0; k16 < 4; k16++) {
            const uint32_t kb = k16 * 32;
            uint32_t ah[2][4], al[2][4];
            LDSM4(ah[0], aoffH + kb);
            LDSM4(ah[1], aoffH + kb + 16*TS*2);
            LDSM4(al[0], aoffL + kb);
            LDSM4(al[1], aoffL + kb + 16*TS*2);
#pragma unroll
            for (int nq = 0; nq < 4; nq++) {
                uint32_t bhf[4], blf[4];
                LDSM4(bhf, boffH[nq] + kb);
                LDSM4(blf, boffL[nq] + kb);
#pragma unroll
                for (int mi = 0; mi < 2; mi++) {
                    MMA16816(acc[mi][nq*2],   ah[mi], bhf[0], bhf[2]);
                    MMA16816(acc[mi][nq*2+1], ah[mi], bhf[1], bhf[3]);
                    MMA16816(acc[mi][nq*2],   ah[mi], blf[0], blf[2]);
                    MMA16816(acc[mi][nq*2+1], ah[mi], blf[1], blf[3]);
                    MMA16816(acc[mi][nq*2],   al[mi], bhf[0], bhf[2]);
                    MMA16816(acc[mi][nq*2+1], al[mi], bhf[1], bhf[3]);
                }
            }
        }

        // fold this 128-k block's scores into running max/sum
#pragma unroll
        for (int mi = 0; mi < 2; mi++) {
            float m0 = -INF_F, m1 = -INF_F, s0 = 0.f, s1 = 0.f;
#pragma unroll
            for (int ni = 0; ni < 8; ni++) {
                m0 = fmaxf(m0, fmaxf(acc[mi][ni][0], acc[mi][ni][1]));
                s0 += acc[mi][ni][0] + acc[mi][ni][1];
                m1 = fmaxf(m1, fmaxf(acc[mi][ni][2], acc[mi][ni][3]));
                s1 += acc[mi][ni][2] + acc[mi][ni][3];
            }
            rmax_[mi][0] = fmaxf(rmax_[mi][0], m0); rsum_[mi][0] += s0;
            rmax_[mi][1] = fmaxf(rmax_[mi][1], m1); rsum_[mi][1] += s1;
        }
    }

    // reduce across the 4 lanes of each quad (same row, diff cols)
#pragma unroll
    for (int mi = 0; mi < 2; mi++)
#pragma unroll
        for (int hf = 0; hf < 2; hf++) {
            float m = rmax_[mi][hf], s = rsum_[mi][hf];
#pragma unroll
            for (int off = 1; off <= 2; off <<= 1) {
                m = fmaxf(m, __shfl_xor_sync(0xffffffffu, m, off));
                s += __shfl_xor_sync(0xffffffffu, s, off);
            }
            rmax_[mi][hf] = m; rsum_[mi][hf] = s;
        }
    if ((lane & 3) == 0) {
        int r0 = lane >> 2;
#pragma unroll
        for (int mi = 0; mi < 2; mi++)
#pragma unroll
            for (int hf = 0; hf < 2; hf++) {
                int row = wm + mi*16 + hf*8 + r0;
                redmax[wid & 1][row] = rmax_[mi][hf];
                redsum[wid & 1][row] = rsum_[mi][hf];
            }
    }
    __syncthreads();
    if (tid < 128) {
        float m = fmaxf(redmax[0][tid], redmax[1][tid]);
        float s = redsum[0][tid] + redsum[1][tid];
        g_M[(size_t)bh*L_ + q0 + tid] = m - s * (1.0f/L_);
    }
}

// ============================================================
__global__ __launch_bounds__(256)
void topk_warp_kernel()
{
    const int warp = threadIdx.x >> 5, lane = threadIdx.x & 31;
    const int bh = blockIdx.x * 8 + warp;
    const float* Mp = g_M + (size_t)bh*L_;
    float v[32];
#pragma unroll
    for (int j = 0; j < 32; j++) v[j] = Mp[j*32 + lane];

    for (int it = 0; it < U_; it++) {
        float bv = v[0]; int bj = 0;
#pragma unroll
        for (int j = 1; j < 32; j++)
            if (v[j] > bv) { bv = v[j]; bj = j; }
        int bk = bj*32 + lane;
#pragma unroll
        for (int off = 16; off; off >>= 1) {
            float ov = __shfl_xor_sync(0xffffffffu, bv, off);
            int   ok = __shfl_xor_sync(0xffffffffu, bk, off);
            if (ov > bv || (ov == bv && ok < bk)) { bv = ov; bk = ok; }
        }
        if (lane == 0) g_idx[bh*U_ + it] = bk;
        int cj = bk >> 5;
        bool mine = ((bk & 31) == lane);
#pragma unroll
        for (int j = 0; j < 32; j++)
            if (mine && j == cj) v[j] = -INF_F;
    }
}

// ============================================================
__global__ __launch_bounds__(256)
void vmean_kernel()
{
    const int bh = blockIdx.x, tid = threadIdx.x;
    const int d = tid & 63, part = tid >> 6;
    const float* vp = g_v + (size_t)bh*L_*D_;
    float acc = 0.f;
    for (int l = part*256; l < part*256 + 256; l++)
        acc += vp[(size_t)l*D_ + d];
    __shared__ float red[4][64];
    red[part][d] = acc;
    __syncthreads();
    if (tid < 64)
        g_vm[bh*64 + tid] =
            (red[0][tid] + red[1][tid] + red[2][tid] + red[3][tid]) * (1.0f/L_);
}

__global__ void zero_kernel()
{
    int t = blockIdx.x*256 + threadIdx.x;
    if (t < B_*L_) g_flag[t] = 0;
    if (t < B_)    g_cnt[t]  = 0;
}

__global__ void compact_kernel()
{
    int t = blockIdx.x*256 + threadIdx.x;
    if (t >= BH_*U_) return;
    int bh = t / U_;
    int b  = bh >> 3;
    int row = g_idx[t];
    if (atomicExch(&g_flag[b*L_ + row], 1) == 0) {
        int p = atomicAdd(&g_cnt[b], 1);
        g_rows[b*L_ + p] = row;
    }
}

__global__ __launch_bounds__(256)
void x2init_kernel()
{
    const int b = blockIdx.x, t = blockIdx.y, tid = threadIdx.x;
    __shared__ float vms[F_];
    for (int f = tid; f < F_; f += 256)
        vms[f] = g_vm[(b*H_ + (f >> 6))*64 + (f & 63)];
    __syncthreads();
    const int cnt = g_cnt[b];
    int hiR = t*128 + 128; if (hiR > cnt) hiR = cnt;
    for (int ri = t*128; ri < hiR; ri++) {
        int l = g_rows[b*L_ + ri];
        float* p = g_x2 + ((size_t)b*L_ + l)*F_;
        p[tid]       = vms[tid];
        p[tid + 256] = vms[tid + 256];
    }
}

// ============================================================
__global__ __launch_bounds__(256)
void sp_scores_kernel(const int* __restrict__ mask)
{
    __shared__ float qs[U_][64];
    __shared__ float Ks[128][68];
    __shared__ int   sidx[U_];
    const int bh = blockIdx.x, tid = threadIdx.x;
    const int b = bh >> 3;
    const int kt0 = blockIdx.y << 7;
    const float* qp = g_q + (size_t)bh*L_*D_;
    const float* kp = g_k + (size_t)bh*L_*D_;
    float* scp = g_sc + (size_t)bh*U_*L_;
    const int* mrow = mask + b*L_;

    if (tid < U_) sidx[tid] = g_idx[bh*U_ + tid];
    __syncthreads();
    for (int i = tid; i < U_*16; i += 256) {
        int u = i >> 4, dc = (i & 15) << 2;
        *(float4*)&qs[u][dc] = *(const float4*)(qp + (size_t)sidx[u]*D_ + dc);
    }
    for (int i = tid; i < 128*16; i += 256) {
        int k = i >> 4, dc = (i & 15) << 2;
        *(float4*)&Ks[k][dc] = *(const float4*)(kp + (size_t)(kt0 + k)*D_ + dc);
    }
    __syncthreads();

    for (int p = tid; p < U_*128; p += 256) {
        int u = p >> 7, kk = p & 127;
        float s = 0.f;
#pragma unroll
        for (int dc = 0; dc < 64; dc += 4) {
            float4 a = *(const float4*)&qs[u][dc];
            float4 c = *(const float4*)&Ks[kk][dc];
            s += a.x*c.x + a.y*c.y + a.z*c.z + a.w*c.w;
        }
        int k = kt0 + kk;
        s *= 0.125f;
        if (mrow[k] == 0) s = -INF_F;
        scp[(size_t)u*L_ + k] = s;
    }
}

__global__ __launch_bounds__(256)
void sp_softmax_kernel()
{
    const int bh = blockIdx.x, tid = threadIdx.x;
    float* scp = g_sc + (size_t)bh*U_*L_;
    const int wid = tid >> 5, lane = tid & 31;
    for (int u = wid; u < U_; u += 8) {
        float mx = -INF_F;
        for (int k = lane; k < L_; k += 32)
            mx = fmaxf(mx, scp[(size_t)u*L_ + k]);
#pragma unroll
        for (int off = 16; off; off >>= 1)
            mx = fmaxf(mx, __shfl_xor_sync(0xffffffffu, mx, off));
        float sm = 0.f;
        for (int k = lane; k < L_; k += 32) {
            float s = scp[(size_t)u*L_ + k];
            sm += (s == -INF_F) ? 0.f : expf(s - mx);
        }
#pragma unroll
        for (int off = 16; off; off >>= 1)
            sm += __shfl_xor_sync(0xffffffffu, sm, off);
        float inv = (sm > 0.f) ? 1.0f / sm : 0.f;
        for (int k = lane; k < L_; k += 32) {
            float s = scp[(size_t)u*L_ + k];
            float pv = (s == -INF_F || mx == -INF_F) ? 0.f : expf(s - mx) * inv;
            scp[(size_t)u*L_ + k] = pv;
        }
    }
}

__global__ __launch_bounds__(256)
void sp_ctx_kernel()
{
    __shared__ float ps[U_][64];
    __shared__ float cb[U_][64];
    __shared__ int   sidx[U_];
    const int bh = blockIdx.x, tid = threadIdx.x;
    const int b = bh >> 3, h = bh & 7;
    const float* vp = g_v + (size_t)bh*L_*D_;
    const float* scp = g_sc + (size_t)bh*U_*L_;
    if (tid < U_) sidx[tid] = g_idx[bh*U_ + tid];

    const int d = tid & 63, part = tid >> 6;
    float acc[U_];
#pragma unroll
    for (int u = 0; u < U_; u++) acc[u] = 0.f;

    for (int kt = 0; kt < L_; kt += 64) {
        __syncthreads();
        for (int i = tid; i < U_*64; i += 256) {
            int u = i >> 6, kk = i & 63;
            ps[u][kk] = scp[(size_t)u*L_ + kt + kk];
        }
        __syncthreads();
        for (int kk = part*16; kk < part*16 + 16; kk++) {
            float v = vp[(size_t)(kt + kk)*D_ + d];
#pragma unroll
            for (int u = 0; u < U_; u++)
                acc[u] += ps[u][kk] * v;
        }
    }
    __syncthreads();
    for (int p2 = 0; p2 < 4; p2++) {
        if (part == p2) {
#pragma unroll
            for (int u = 0; u < U_; u++) {
                if (p2 == 0) cb[u][d] = acc[u];
                else         cb[u][d] += acc[u];
            }
        }
        __syncthreads();
    }
    float* x2 = g_x2 + (size_t)b*L_*F_ + h*D_;
    for (int i = tid; i < U_*64; i += 256) {
        int u = i >> 6, dd = i & 63;
        x2[(size_t)sidx[u]*F_ + dd] = cb[u][dd];
    }
}

// ============================================================
__global__ __launch_bounds__(256)
void mean_out_kernel(const float* __restrict__ Wo, const float* __restrict__ bo)
{
    const int b = blockIdx.x, tid = threadIdx.x;
    __shared__ float vms[F_];
    for (int f = tid; f < F_; f += 256)
        vms[f] = g_vm[(b*H_ + (f >> 6))*64 + (f & 63)];
    __syncthreads();
    for (int n = tid; n < F_; n += 256) {
        float s = bo[n];
        const float* w = Wo + (size_t)n*F_;
        for (int f = 0; f < F_; f += 4) {
            float4 wv = *(const float4*)(w + f);
            s += vms[f]*wv.x + vms[f+1]*wv.y + vms[f+2]*wv.z + vms[f+3]*wv.w;
        }
        g_om[b*F_ + n] = s;
    }
}

__global__ __launch_bounds__(256)
void bcast_kernel(float* __restrict__ out)
{
    const int b = blockIdx.x, l0 = blockIdx.y << 3, tid = threadIdx.x;
    __shared__ float om[F_];
    for (int f = tid; f < F_; f += 256) om[f] = g_om[b*F_ + f];
    __syncthreads();
    float2 v = *(const float2*)&om[tid*2];
    float* base = out + ((size_t)b*L_ + l0)*F_;
#pragma unroll
    for (int rr = 0; rr < 8; rr++)
        *(float2*)(base + (size_t)rr*F_ + tid*2) = v;
}

// ============================================================
__global__ __launch_bounds__(256, 2)
void gemm_rows_kernel(const float* __restrict__ W,
                      const float* __restrict__ bias,
                      float* __restrict__ out)
{
    const int b = blockIdx.y / 3;
    const int t = blockIdx.y % 3;
    const int cnt = g_cnt[b];
    if (t * 128 >= cnt) return;

    __shared__ __align__(16) float As[2][16][132];
    __shared__ __align__(16) float Bs[2][16][132];
    __shared__ int rows_s[128];

    const int tid = threadIdx.x;
    if (tid < 128) {
        int gi = t*128 + tid;
        rows_s[tid] = (gi < cnt) ? g_rows[b*L_ + gi] : g_rows[b*L_];
    }
    __syncthreads();

    const float* X = g_x2 + (size_t)b*L_*F_;
    const int tx = tid & 15, ty = tid >> 4;
    const int n0 = blockIdx.x * 128;
    const int r  = tid >> 2;
    const int kc = (tid & 3) << 2;
    const int mo = r << 1;
    const int l0r = rows_s[r], l1r = rows_s[r + 64];

    u64 acc[4][8];
#pragma unroll
    for (int i = 0; i < 4; i++)
#pragma unroll
        for (int j = 0; j < 8; j++) acc[i][j] = 0ULL;

    float4 ra0, ra1, rb0, rb1;
    ra0 = *(const float4*)(X + (size_t)l0r*F_ + kc);
    ra1 = *(const float4*)(X + (size_t)l1r*F_ + kc);
    rb0 = *(const float4*)(W + (size_t)(n0 + r)*F_ + kc);
    rb1 = *(const float4*)(W + (size_t)(n0 + r + 64)*F_ + kc);

#define GSTORE(bsel) do { \
    As[bsel][kc+0][mo]   = ra0.x; As[bsel][kc+1][mo]   = ra0.y; \
    As[bsel][kc+2][mo]   = ra0.z; As[bsel][kc+3][mo]   = ra0.w; \
    As[bsel][kc+0][mo+1] = ra1.x; As[bsel][kc+1][mo+1] = ra1.y; \
    As[bsel][kc+2][mo+1] = ra1.z; As[bsel][kc+3][mo+1] = ra1.w; \
    Bs[bsel][kc+0][r]    = rb0.x; Bs[bsel][kc+1][r]    = rb0.y; \
    Bs[bsel][kc+2][r]    = rb0.z; Bs[bsel][kc+3][r]    = rb0.w; \
    Bs[bsel][kc+0][r+64] = rb1.x; Bs[bsel][kc+1][r+64] = rb1.y; \
    Bs[bsel][kc+2][r+64] = rb1.z; Bs[bsel][kc+3][r+64] = rb1.w; } while(0)

    GSTORE(0);
    __syncthreads();

    for (int c = 0; c < 32; c++) {
        if (c < 31) {
            int kb = (c + 1) << 4;
            ra0 = *(const float4*)(X + (size_t)l0r*F_ + kb + kc);
            ra1 = *(const float4*)(X + (size_t)l1r*F_ + kb + kc);
            rb0 = *(const float4*)(W + (size_t)(n0 + r)*F_ + kb + kc);
            rb1 = *(const float4*)(W + (size_t)(n0 + r + 64)*F_ + kb + kc);
        }
        const int bsel = c & 1;
#pragma unroll
        for (int kk = 0; kk < 16; kk++) {
            ulonglong2 a01 = *(const ulonglong2*)&As[bsel][kk][ty << 3];
            ulonglong2 a23 = *(const ulonglong2*)&As[bsel][kk][(ty << 3) + 4];
            float4 b0 = *(const float4*)&Bs[bsel][kk][tx << 3];
            float4 b1 = *(const float4*)&Bs[bsel][kk][(tx << 3) + 4];
            u64 av[4] = {a01.x, a01.y, a23.x, a23.y};
            u64 bv[8] = {dup2(b0.x), dup2(b0.y), dup2(b0.z), dup2(b0.w),
                         dup2(b1.x), dup2(b1.y), dup2(b1.z), dup2(b1.w)};
#pragma unroll
            for (int i = 0; i < 4; i++)
#pragma unroll
                for (int j = 0; j < 8; j++)
                    fma2(acc[i][j], av[i], bv[j]);
        }
        if (c < 31) GSTORE((c + 1) & 1);
        __syncthreads();
    }
#undef GSTORE

    const int nb = n0 + (tx << 3);
    float bb[8];
#pragma unroll
    for (int j = 0; j < 8; j++) bb[j] = bias[nb + j];

#pragma unroll
    for (int i = 0; i < 4; i++) {
        float lo[8], hi[8];
#pragma unroll
        for (int j = 0; j < 8; j++) {
            float2 tt = unpk(acc[i][j]);
            lo[j] = tt.x + bb[j];
            hi[j] = tt.y + bb[j];
        }
        {
            int l = rows_s[(ty << 2) + i];
            float* p = out + ((size_t)b*L_ + l)*F_ + nb;
            *(float4*)p     = make_float4(lo[0], lo[1], lo[2], lo[3]);
            *(float4*)(p+4) = make_float4(lo[4], lo[5], lo[6], lo[7]);
        }
        {
            int l = rows_s[(ty << 2) + i + 64];
            float* p = out + ((size_t)b*L_ + l)*F_ + nb;
            *(float4*)p     = make_float4(hi[0], hi[1], hi[2], hi[3]);
            *(float4*)(p+4) = make_float4(hi[4], hi[5], hi[6], hi[7]);
        }
    }
}

// ============================================================
extern "C" void kernel_launch(void* const* d_in, const int* in_sizes, int n_in,
                              void* d_out, int out_size)
{
    const float* query = (const float*)d_in[0];
    const float* key   = (const float*)d_in[1];
    const float* value = (const float*)d_in[2];
    const int*   mask  = (const int*)  d_in[3];
    const float* Wq = (const float*)d_in[4];
    const float* bq = (const float*)d_in[5];
    const float* Wk = (const float*)d_in[6];
    const float* bk = (const float*)d_in[7];
    const float* Wv = (const float*)d_in[8];
    const float* bv = (const float*)d_in[9];
    const float* Wo = (const float*)d_in[10];
    const float* bo = (const float*)d_in[11];
    float* out = (float*)d_out;

    float *qd, *kd, *vd;
    cudaGetSymbolAddress((void**)&qd, g_q);
    cudaGetSymbolAddress((void**)&kd, g_k);
    cudaGetSymbolAddress((void**)&vd, g_v);

    cudaFuncSetAttribute(hmma_proj_kernel,
                         cudaFuncAttributeMaxDynamicSharedMemorySize, HM_SMEM);
    cudaFuncSetAttribute(qk_hmma_kernel,
                         cudaFuncAttributeMaxDynamicSharedMemorySize, QK_SMEM);

    zero_kernel<<<64, 256>>>();
    convx_kernel<<<dim3((ML_*F_/4)/256, 3), 256>>>(query, key, value);
    convw_kernel<<<dim3((F_*F_/4)/256, 3), 256>>>(Wq, Wk, Wv);

    hmma_proj_kernel<<<dim3(F_/128, ML_/128, 3), 256, HM_SMEM>>>(qd, kd, vd, bq, bk, bv);

    qk_hmma_kernel<<<dim3(L_/128, BH_), 256, QK_SMEM>>>();

    topk_warp_kernel<<<BH_/8, 256>>>();
    vmean_kernel<<<BH_, 256>>>();
    compact_kernel<<<(BH_*U_ + 255)/256, 256>>>();
    x2init_kernel<<<dim3(B_, 3), 256>>>();

    sp_scores_kernel<<<dim3(BH_, 8), 256>>>(mask);
    sp_softmax_kernel<<<BH_, 256>>>();
    sp_ctx_kernel<<<BH_, 256>>>();

    mean_out_kernel<<<B_, 256>>>(Wo, bo);
    bcast_kernel<<<dim3(B_, L_/8), 256>>>(out);
    gemm_rows_kernel<<<dim3(F_/128, B_*3), 256>>>(Wo, bo, out);
}